// round 7
// baseline (speedup 1.0000x reference)
#include <cuda_runtime.h>
#include <cuda_bf16.h>
#include <cuda_fp16.h>

#define BATCH 4096
#define DIM   1024
#define NS    64
#define LBLK  11
#define NBLK  93          // 93*11 = 1023
#define NCODE 2048

// ---- device-global scratch (static; no runtime alloc) ----
__device__ float  g_E0[NS], g_E1[NS], g_Pi[NS];
__device__ float  g_L1[2 * NS * NS];
__device__ float  g_L2[4 * NS * NS];
__device__ float  g_L4[16 * NS * NS];
__device__ float  g_L8[256 * NS * NS];
__device__ int    g_e1[2], g_e2[4], g_e4[16], g_e8[256], g_e11[NCODE];
// fp8 e4m3 table, permuted: byte(c,o,k) = c*4096 + ((o<32?0:4)+(k>>4))*512 + (o&31)*16 + (k&15)
__device__ uint4  g_Pt4[NCODE * 256];    // 8 MB
__device__ double g_acc;

// ---- fp8 helpers ----
__device__ __forceinline__ unsigned short f2_e4m3x2(float hi, float lo) {
    unsigned short r;
    asm("cvt.rn.satfinite.e4m3x2.f32 %0, %1, %2;" : "=h"(r) : "f"(hi), "f"(lo));
    return r;
}
__device__ __forceinline__ __half2 e4m3x2_h2(unsigned short s) {
    unsigned r;
    asm("cvt.rn.f16x2.e4m3x2 %0, %1;" : "=r"(r) : "h"(s));
    return *(__half2*)&r;
}
__device__ __forceinline__ __half2 as_h2(unsigned w) { return *(__half2*)&w; }

// ============================================================================
// prep: softmaxes + L1 (both y) + L2 (4 products) in ONE kernel, 1024 threads
// ============================================================================
__global__ void __launch_bounds__(1024)
prep_kernel(const float* __restrict__ Tr,
            const float* __restrict__ Em,
            const float* __restrict__ Pi) {
    __shared__ float sL1[2][NS * NS];     // 32 KB
    __shared__ float rowm[NS], rowinv[NS];
    __shared__ float sE[2][NS];
    __shared__ float sred[32];
    __shared__ float sbcA[4];
    __shared__ int   seiA[4];

    const int tid  = threadIdx.x;
    const int lane = tid & 31;
    const int w    = tid >> 5;

    if (tid == 0) g_acc = 0.0;

    // --- T row-softmax params: warp w handles rows w and w+32 ---
#pragma unroll
    for (int rr = 0; rr < 2; rr++) {
        const int r = w + rr * 32;
        const float v0 = Tr[r * NS + lane];
        const float v1 = Tr[r * NS + lane + 32];
        float m = fmaxf(v0, v1);
#pragma unroll
        for (int off = 16; off > 0; off >>= 1)
            m = fmaxf(m, __shfl_xor_sync(0xffffffffu, m, off));
        const float e0 = expf(v0 - m), e1v = expf(v1 - m);
        float s = e0 + e1v;
#pragma unroll
        for (int off = 16; off > 0; off >>= 1)
            s += __shfl_xor_sync(0xffffffffu, s, off);
        if (lane == 0) { rowm[r] = m; rowinv[r] = 1.f / s; }
    }
    // --- E softmax (2 classes) ---
    if (tid < NS) {
        const float a = Em[tid * 2 + 0], b2 = Em[tid * 2 + 1];
        const float mm = fmaxf(a, b2);
        const float ea = expf(a - mm), eb = expf(b2 - mm);
        const float is = 1.f / (ea + eb);
        sE[0][tid] = ea * is;  sE[1][tid] = eb * is;
        g_E0[tid] = ea * is;   g_E1[tid] = eb * is;
    }
    // --- Pi softmax (warp 1) ---
    if (w == 1) {
        const float v0 = Pi[lane], v1 = Pi[lane + 32];
        float m = fmaxf(v0, v1);
#pragma unroll
        for (int off = 16; off > 0; off >>= 1)
            m = fmaxf(m, __shfl_xor_sync(0xffffffffu, m, off));
        const float e0 = expf(v0 - m), e1v = expf(v1 - m);
        float s = e0 + e1v;
#pragma unroll
        for (int off = 16; off > 0; off >>= 1)
            s += __shfl_xor_sync(0xffffffffu, s, off);
        const float inv = 1.f / s;
        g_Pi[lane] = e0 * inv;  g_Pi[lane + 32] = e1v * inv;
    }
    __syncthreads();

    // --- L1_y[k][o] = softmaxT[k][o] * E_y[o], normalized (4 elems/thread/y) ---
    for (int y = 0; y < 2; y++) {
        float vv[4], vmax = 0.f;
#pragma unroll
        for (int i = 0; i < 4; i++) {
            const int idx = tid + i * 1024;
            const int k = idx >> 6, o = idx & 63;
            const float v = expf(Tr[idx] - rowm[k]) * rowinv[k] * sE[y][o];
            vv[i] = v; vmax = fmaxf(vmax, v);
        }
#pragma unroll
        for (int off = 16; off > 0; off >>= 1)
            vmax = fmaxf(vmax, __shfl_xor_sync(0xffffffffu, vmax, off));
        if (lane == 0) sred[w] = vmax;
        __syncthreads();
        if (tid < 32) {
            float m = sred[lane];
#pragma unroll
            for (int off = 16; off > 0; off >>= 1)
                m = fmaxf(m, __shfl_xor_sync(0xffffffffu, m, off));
            if (lane == 0) {
                const int e = (__float_as_int(m) >> 23) - 127;
                seiA[y] = e;  g_e1[y] = e;
                sbcA[y] = __int_as_float((127 - e) << 23);
            }
        }
        __syncthreads();
        const float sc = sbcA[y];
#pragma unroll
        for (int i = 0; i < 4; i++) {
            const int idx = tid + i * 1024;
            sL1[y][idx] = vv[i] * sc;
            g_L1[y * NS * NS + idx] = vv[i] * sc;
        }
        __syncthreads();
    }

    // --- L2[g] = L1[g>>1] @ L1[g&1] : group g = tid>>8 (256 threads each) ---
    {
        const int g    = tid >> 8;
        const int gtid = tid & 255;
        const int j    = gtid & 63;
        const int h    = gtid >> 6;
        const float* __restrict__ A = sL1[g >> 1];
        const float* __restrict__ B = sL1[g & 1];

        float out[16], mx = 0.f;
#pragma unroll
        for (int ii = 0; ii < 4; ii++) {
            const int r0 = h * 16 + 4 * ii;
            float a0 = 0.f, a1 = 0.f, a2 = 0.f, a3 = 0.f;
            for (int k = 0; k < NS; k++) {
                const float bv = B[k * NS + j];
                a0 = fmaf(A[(r0 + 0) * NS + k], bv, a0);
                a1 = fmaf(A[(r0 + 1) * NS + k], bv, a1);
                a2 = fmaf(A[(r0 + 2) * NS + k], bv, a2);
                a3 = fmaf(A[(r0 + 3) * NS + k], bv, a3);
            }
            out[4 * ii + 0] = a0; out[4 * ii + 1] = a1;
            out[4 * ii + 2] = a2; out[4 * ii + 3] = a3;
            mx = fmaxf(mx, fmaxf(fmaxf(a0, a1), fmaxf(a2, a3)));
        }
#pragma unroll
        for (int off = 16; off > 0; off >>= 1)
            mx = fmaxf(mx, __shfl_xor_sync(0xffffffffu, mx, off));
        __syncthreads();          // sred reuse
        if (lane == 0) sred[w] = mx;
        __syncthreads();
        if (tid < 4) {
            float m = sred[8 * tid];
#pragma unroll
            for (int q = 1; q < 8; q++) m = fmaxf(m, sred[8 * tid + q]);
            const int e = (__float_as_int(m) >> 23) - 127;
            sbcA[tid] = __int_as_float((127 - e) << 23);
            g_e2[tid] = seiA[tid >> 1] + seiA[tid & 1] + e;
        }
        __syncthreads();
        const float sc = sbcA[g];
#pragma unroll
        for (int t = 0; t < 16; t++)
            g_L2[g * NS * NS + (h * 16 + t) * NS + j] = out[t] * sc;
    }
}

// ============================================================================
// combine: stage 1: L4 = L2@L2 (grid 16); stage 2: L8 = L4@L4 (grid 256)
// ============================================================================
__global__ void __launch_bounds__(256) combine_kernel(int stage) {
    __shared__ float As[NS * NS];
    __shared__ float Bs[NS * NS];
    __shared__ float sred[8];
    __shared__ float sbc;
    __shared__ int   sei;

    const float *A; float *C; const int *eA; int *eC; int bitsB;
    if (stage == 1) { A = g_L2; eA = g_e2; C = g_L4; eC = g_e4; bitsB = 2; }
    else            { A = g_L4; eA = g_e4; C = g_L8; eC = g_e8; bitsB = 4; }

    const int c = blockIdx.x;
    const int a = c >> bitsB;
    const int b = c & ((1 << bitsB) - 1);
    const int tid  = threadIdx.x;
    const int lane = tid & 31;
    const int w    = tid >> 5;

    {
        const float4* Ag = (const float4*)(A + a * NS * NS);
        const float4* Bg = (const float4*)(A + b * NS * NS);
        float4* As4 = (float4*)As; float4* Bs4 = (float4*)Bs;
#pragma unroll
        for (int i = 0; i < 4; i++) { As4[tid + 256 * i] = Ag[tid + 256 * i];
                                      Bs4[tid + 256 * i] = Bg[tid + 256 * i]; }
    }
    __syncthreads();

    const int j = tid & 63;
    const int h = tid >> 6;
    float out[16], mx = 0.f;
#pragma unroll
    for (int ii = 0; ii < 4; ii++) {
        const int r0 = h * 16 + 4 * ii;
        float a0 = 0.f, a1 = 0.f, a2 = 0.f, a3 = 0.f;
        for (int k = 0; k < NS; k++) {
            const float bv = Bs[k * NS + j];
            a0 = fmaf(As[(r0 + 0) * NS + k], bv, a0);
            a1 = fmaf(As[(r0 + 1) * NS + k], bv, a1);
            a2 = fmaf(As[(r0 + 2) * NS + k], bv, a2);
            a3 = fmaf(As[(r0 + 3) * NS + k], bv, a3);
        }
        out[4 * ii + 0] = a0; out[4 * ii + 1] = a1;
        out[4 * ii + 2] = a2; out[4 * ii + 3] = a3;
        mx = fmaxf(mx, fmaxf(fmaxf(a0, a1), fmaxf(a2, a3)));
    }
#pragma unroll
    for (int off = 16; off > 0; off >>= 1)
        mx = fmaxf(mx, __shfl_xor_sync(0xffffffffu, mx, off));
    if (lane == 0) sred[w] = mx;
    __syncthreads();
    if (tid == 0) {
        float m = sred[0];
#pragma unroll
        for (int q = 1; q < 8; q++) m = fmaxf(m, sred[q]);
        const int e = (__float_as_int(m) >> 23) - 127;
        sbc = __int_as_float((127 - e) << 23);
        sei = e;
    }
    __syncthreads();
    const float sc = sbc;
#pragma unroll
    for (int t = 0; t < 16; t++)
        C[c * NS * NS + (h * 16 + t) * NS + j] = out[t] * sc;
    if (tid == 0) eC[c] = eA[a] + eA[b] + sei;
}

// ============================================================================
// final: per block c2: Tmp = L8[c2>>2] @ L2[c2&3]; codes 2*c2+d = Tmp @ L1[d]
// writes permuted e4m3 table + g_e11.  grid 1024, 256 threads, 48KB smem.
// ============================================================================
__global__ void __launch_bounds__(256) final_kernel() {
    __shared__ float As[NS * NS];
    __shared__ float Bs[NS * NS];
    __shared__ float Cs[NS * NS];

    const int c2 = blockIdx.x;
    const int a  = c2 >> 2;
    const int b  = c2 & 3;
    const int tid  = threadIdx.x;
    const int lane = tid & 31;
    const int w    = tid >> 5;
    const int j = tid & 63;
    const int h = tid >> 6;

    {
        const float4* Ag = (const float4*)(g_L8 + a * NS * NS);
        const float4* Bg = (const float4*)(g_L2 + b * NS * NS);
        float4* As4 = (float4*)As; float4* Bs4 = (float4*)Bs;
#pragma unroll
        for (int i = 0; i < 4; i++) { As4[tid + 256 * i] = Ag[tid + 256 * i];
                                      Bs4[tid + 256 * i] = Bg[tid + 256 * i]; }
    }
    __syncthreads();

    // GEMM1: Tmp = L8 @ L2 -> Cs (no normalization needed; values bounded)
#pragma unroll
    for (int ii = 0; ii < 4; ii++) {
        const int r0 = h * 16 + 4 * ii;
        float a0 = 0.f, a1 = 0.f, a2 = 0.f, a3 = 0.f;
        for (int k = 0; k < NS; k++) {
            const float bv = Bs[k * NS + j];
            a0 = fmaf(As[(r0 + 0) * NS + k], bv, a0);
            a1 = fmaf(As[(r0 + 1) * NS + k], bv, a1);
            a2 = fmaf(As[(r0 + 2) * NS + k], bv, a2);
            a3 = fmaf(As[(r0 + 3) * NS + k], bv, a3);
        }
        Cs[(r0 + 0) * NS + j] = a0; Cs[(r0 + 1) * NS + j] = a1;
        Cs[(r0 + 2) * NS + j] = a2; Cs[(r0 + 3) * NS + j] = a3;
    }
    __syncthreads();

    // reload As = L1[0], Bs = L1[1]
    {
        const float4* Ag = (const float4*)(g_L1);
        const float4* Bg = (const float4*)(g_L1 + NS * NS);
        float4* As4 = (float4*)As; float4* Bs4 = (float4*)Bs;
#pragma unroll
        for (int i = 0; i < 4; i++) { As4[tid + 256 * i] = Ag[tid + 256 * i];
                                      Bs4[tid + 256 * i] = Bg[tid + 256 * i]; }
    }
    __syncthreads();

    const int eab = g_e8[a] + g_e2[b];

#pragma unroll
    for (int d = 0; d < 2; d++) {
        float* Src = d ? Bs : As;     // reduction scratch reuses Src after GEMM
        float out[16], mx = 0.f;
#pragma unroll
        for (int ii = 0; ii < 4; ii++) {
            const int r0 = h * 16 + 4 * ii;
            float a0 = 0.f, a1 = 0.f, a2 = 0.f, a3 = 0.f;
            for (int k = 0; k < NS; k++) {
                const float bv = Src[k * NS + j];
                a0 = fmaf(Cs[(r0 + 0) * NS + k], bv, a0);
                a1 = fmaf(Cs[(r0 + 1) * NS + k], bv, a1);
                a2 = fmaf(Cs[(r0 + 2) * NS + k], bv, a2);
                a3 = fmaf(Cs[(r0 + 3) * NS + k], bv, a3);
            }
            out[4 * ii + 0] = a0; out[4 * ii + 1] = a1;
            out[4 * ii + 2] = a2; out[4 * ii + 3] = a3;
            mx = fmaxf(mx, fmaxf(fmaxf(a0, a1), fmaxf(a2, a3)));
        }
#pragma unroll
        for (int off = 16; off > 0; off >>= 1)
            mx = fmaxf(mx, __shfl_xor_sync(0xffffffffu, mx, off));
        __syncthreads();                 // all GEMM reads of Src done
        if (lane == 0) Src[w] = mx;
        __syncthreads();
        if (tid == 0) {
            float m = Src[0];
#pragma unroll
            for (int q = 1; q < 8; q++) m = fmaxf(m, Src[q]);
            const int e = (__float_as_int(m) >> 23) - 127;
            Src[8] = __int_as_float((127 - e) << 23);
            Src[9] = __int_as_float(e);
        }
        __syncthreads();
        const float sc = Src[8];
        const int   ef = __float_as_int(Src[9]);

        const int code = c2 * 2 + d;
        // permuted e4m3 write: thread owns rows k = h*16..h*16+15 of column j
        unsigned wd[4];
#pragma unroll
        for (int q = 0; q < 4; q++) {
            const int t = 4 * q;
            const unsigned p01 = f2_e4m3x2(out[t + 1] * sc, out[t + 0] * sc);
            const unsigned p23 = f2_e4m3x2(out[t + 3] * sc, out[t + 2] * sc);
            wd[q] = p01 | (p23 << 16);
        }
        uint4* dst = (uint4*)((char*)g_Pt4 + (size_t)code * 4096
                              + ((j < 32 ? 0 : 4) + h) * 512 + (j & 31) * 16);
        *dst = make_uint4(wd[0], wd[1], wd[2], wd[3]);
        if (tid == 0) g_e11[code] = eab + g_e1[d] + ef;
        __syncthreads();                 // protect Src scratch before next d
    }
}

// ============================================================================
// main: one warp per element; inline ballot codes; fp8 table, half2 matvec
// ============================================================================
#define PREFETCH(MB, c)                                                       \
    {                                                                         \
        const uint4* __restrict__ tp = g_Pt4 + (size_t)(c) * 256 + lane;      \
        _Pragma("unroll")                                                     \
        for (int i = 0; i < 8; i++) MB[i] = tp[i * 32];                       \
    }

#define PROC8(u, av0, av1, acc)                                               \
    acc = __hfma2(e4m3x2_h2((unsigned short)(u).x),         as_h2((av0).x), acc); \
    acc = __hfma2(e4m3x2_h2((unsigned short)((u).x >> 16)), as_h2((av0).y), acc); \
    acc = __hfma2(e4m3x2_h2((unsigned short)(u).y),         as_h2((av0).z), acc); \
    acc = __hfma2(e4m3x2_h2((unsigned short)((u).y >> 16)), as_h2((av0).w), acc); \
    acc = __hfma2(e4m3x2_h2((unsigned short)(u).z),         as_h2((av1).x), acc); \
    acc = __hfma2(e4m3x2_h2((unsigned short)((u).z >> 16)), as_h2((av1).y), acc); \
    acc = __hfma2(e4m3x2_h2((unsigned short)(u).w),         as_h2((av1).z), acc); \
    acc = __hfma2(e4m3x2_h2((unsigned short)((u).w >> 16)), as_h2((av1).w), acc);

#define PACKSTORE(PP)                                                         \
    {                                                                         \
        const float ev = __shfl_sync(0xffffffffu, s_lo, 0);                   \
        int e = (__float_as_int(ev) >> 23) - 125;                             \
        e = max(-120, min(120, e));                                           \
        const float rsc = __int_as_float((127 - e) << 23);                    \
        s_lo *= rsc; s_hi *= rsc; ce += e;                                    \
        const float lo0 = __shfl_sync(0xffffffffu, s_lo, (2 * lane) & 31);    \
        const float lo1 = __shfl_sync(0xffffffffu, s_lo, (2 * lane + 1) & 31);\
        const float hi0 = __shfl_sync(0xffffffffu, s_hi, (2 * lane) & 31);    \
        const float hi1 = __shfl_sync(0xffffffffu, s_hi, (2 * lane + 1) & 31);\
        const float x0 = lane < 16 ? lo0 : hi0;                               \
        const float x1 = lane < 16 ? lo1 : hi1;                               \
        s_ah[wid][PP][lane] = __floats2half2_rn(x0, x1);                      \
        __syncwarp();                                                         \
    }

#define COMPUTE(MB, CODE)                                                     \
    {                                                                         \
        const uint4* __restrict__ ah = (const uint4*)s_ah[wid][p];            \
        uint4 au[8];                                                          \
        _Pragma("unroll")                                                     \
        for (int q = 0; q < 8; q++) au[q] = ah[q];                            \
        __half2 c0 = __float2half2_rn(0.f), c1 = c0, c2 = c0, c3 = c0;        \
        __half2 d0 = c0, d1 = c0, d2 = c0, d3 = c0;                           \
        PROC8(MB[0], au[0], au[1], c0)                                        \
        PROC8(MB[1], au[2], au[3], c1)                                        \
        PROC8(MB[2], au[4], au[5], c2)                                        \
        PROC8(MB[3], au[6], au[7], c3)                                        \
        PROC8(MB[4], au[0], au[1], d0)                                        \
        PROC8(MB[5], au[2], au[3], d1)                                        \
        PROC8(MB[6], au[4], au[5], d2)                                        \
        PROC8(MB[7], au[6], au[7], d3)                                        \
        const __half2 tc = __hadd2(__hadd2(c0, c1), __hadd2(c2, c3));         \
        const __half2 td = __hadd2(__hadd2(d0, d1), __hadd2(d2, d3));         \
        s_lo = __low2float(tc) + __high2float(tc);                            \
        s_hi = __low2float(td) + __high2float(td);                            \
        ce += g_e11[CODE];                                                    \
        p ^= 1;                                                               \
        PACKSTORE(p)                                                          \
    }

__device__ __forceinline__ int getcode(const unsigned* __restrict__ bw, int j) {
    const int base = 1 + LBLK * j;
    const unsigned lo = bw[base >> 5];
    const unsigned hi = bw[(base >> 5) + 1];
    return (int)(__brev(__funnelshift_r(lo, hi, base & 31)) >> 21);
}

__global__ void __launch_bounds__(128)
hmm_main_kernel(const int* __restrict__ y) {
    __shared__ __align__(16) __half2 s_ah[4][2][32];
    __shared__ unsigned s_bw[4][34];

    const int tid  = threadIdx.x;
    const int lane = tid & 31;
    const int wid  = tid >> 5;
    const int b    = blockIdx.x * 4 + wid;
    const int* __restrict__ yrow = y + b * DIM;

    // build 1024-bit observation string via ballots
#pragma unroll
    for (int ch = 0; ch < 32; ch++) {
        const unsigned w = __ballot_sync(0xffffffffu, yrow[ch * 32 + lane]);
        if (lane == 0) s_bw[wid][ch] = w;
    }
    if (lane == 0) { s_bw[wid][32] = 0u; s_bw[wid][33] = 0u; }
    __syncwarp();
    const unsigned* __restrict__ bw = s_bw[wid];

    const int y0 = (int)(bw[0] & 1u);
    float s_lo = g_Pi[lane]      * (y0 ? g_E1[lane]      : g_E0[lane]);
    float s_hi = g_Pi[lane + 32] * (y0 ? g_E1[lane + 32] : g_E0[lane + 32]);

    int ce = 0, p = 0;
    PACKSTORE(0)

    uint4 mA[8], mB[8];
    int cA = getcode(bw, 0), cB;
    PREFETCH(mA, cA)

    for (int jj = 0; jj < 92; jj += 2) {
        cB = getcode(bw, jj + 1);
        PREFETCH(mB, cB)
        COMPUTE(mA, cA)
        cA = getcode(bw, jj + 2);
        PREFETCH(mA, cA)
        COMPUTE(mB, cB)
    }
    COMPUTE(mA, cA)   // j = 92 (prefetched at jj = 90)

    float v = s_lo + s_hi;
#pragma unroll
    for (int off = 16; off > 0; off >>= 1)
        v += __shfl_xor_sync(0xffffffffu, v, off);

    if (lane == 0) {
        const double logp = (double)logf(v) + (double)ce * 0.6931471805599453;
        atomicAdd(&g_acc, logp);
    }
}

__global__ void fin_kernel(float* out) {
    out[0] = (float)(g_acc * (1.0 / 4096.0));
}

extern "C" void kernel_launch(void* const* d_in, const int* in_sizes, int n_in,
                              void* d_out, int out_size) {
    const int*   y  = (const int*)  d_in[0];
    const float* Tr = (const float*)d_in[1];
    const float* Em = (const float*)d_in[2];
    const float* Pi = (const float*)d_in[3];

    prep_kernel<<<1, 1024>>>(Tr, Em, Pi);
    combine_kernel<<<16, 256>>>(1);     // L4 = L2@L2
    combine_kernel<<<256, 256>>>(2);    // L8 = L4@L4
    final_kernel<<<1024, 256>>>();      // L11 table (e4m3, permuted) + e11
    hmm_main_kernel<<<BATCH / 4, 128>>>(y);
    fin_kernel<<<1, 1>>>((float*)d_out);
}

// round 8
// speedup vs baseline: 1.3191x; 1.3191x over previous
#include <cuda_runtime.h>
#include <cuda_bf16.h>
#include <cuda_fp16.h>

#define BATCH 4096
#define DIM   1024
#define NS    64
#define LBLK  11
#define NCODE 2048

typedef unsigned long long u64;

// ---- device-global scratch (static; no runtime alloc) ----
__device__ float  g_E0[NS], g_E1[NS], g_Pi[NS];
__device__ float  g_L1[2 * NS * NS];                  // normal [k][o]
__device__ float  g_L2[4 * NS * NS],  g_L2t[4 * NS * NS];
__device__ float  g_L4[16 * NS * NS], g_L4t[16 * NS * NS];
__device__ float  g_L8t[256 * NS * NS];               // only transposed needed
__device__ int    g_e1[2], g_e2[4], g_e4[16], g_e8[256], g_e11[NCODE];
// fp8 e4m3 table, permuted: byte(c,o,k) = c*4096 + ((o<32?0:4)+(k>>4))*512 + (o&31)*16 + (k&15)
__device__ uint4  g_Pt4[NCODE * 256];    // 8 MB
__device__ double g_acc;

// ---- packed helpers ----
__device__ __forceinline__ u64 pk2(float lo, float hi) {
    u64 r; asm("mov.b64 %0, {%1,%2};" : "=l"(r) : "f"(lo), "f"(hi)); return r;
}
__device__ __forceinline__ void upk2(u64 v, float &lo, float &hi) {
    asm("mov.b64 {%0,%1}, %2;" : "=f"(lo), "=f"(hi) : "l"(v));
}
__device__ __forceinline__ u64 fma2(u64 a, u64 b, u64 c) {
    u64 d; asm("fma.rn.f32x2 %0, %1, %2, %3;" : "=l"(d) : "l"(a), "l"(b), "l"(c)); return d;
}
__device__ __forceinline__ unsigned short f2_e4m3x2(float hi, float lo) {
    unsigned short r;
    asm("cvt.rn.satfinite.e4m3x2.f32 %0, %1, %2;" : "=h"(r) : "f"(hi), "f"(lo));
    return r;
}
__device__ __forceinline__ __half2 e4m3x2_h2(unsigned short s) {
    unsigned r;
    asm("cvt.rn.f16x2.e4m3x2 %0, %1;" : "=r"(r) : "h"(s));
    return *(__half2*)&r;
}
__device__ __forceinline__ __half2 as_h2(unsigned w) { return *(__half2*)&w; }

// ---- core GEMM fragment: thread owns rows h*16..h*16+15 (pairs), col j ----
// At: transposed A in smem, At[k*strideF + r] = A[r][k]; strideF*4 must be mult of 16
// B : normal [k*64 + j]. acc[p] packs rows (h*16+2p, h*16+2p+1), accumulated over k.
__device__ __forceinline__ void gemm16(const float* __restrict__ At, int strideF,
                                       const float* __restrict__ B,
                                       int j, int h, u64 acc[8]) {
#pragma unroll
    for (int p = 0; p < 8; p++) acc[p] = 0ull;
#pragma unroll 16
    for (int k = 0; k < NS; k++) {
        const ulonglong2* __restrict__ ar =
            (const ulonglong2*)(At + k * strideF) + h * 4;
        const ulonglong2 q0 = ar[0], q1 = ar[1], q2 = ar[2], q3 = ar[3];
        const float bv = B[k * NS + j];
        const u64 bb = pk2(bv, bv);
        acc[0] = fma2(q0.x, bb, acc[0]); acc[1] = fma2(q0.y, bb, acc[1]);
        acc[2] = fma2(q1.x, bb, acc[2]); acc[3] = fma2(q1.y, bb, acc[3]);
        acc[4] = fma2(q2.x, bb, acc[4]); acc[5] = fma2(q2.y, bb, acc[5]);
        acc[6] = fma2(q3.x, bb, acc[6]); acc[7] = fma2(q3.y, bb, acc[7]);
    }
}

// ============================================================================
// prep: softmaxes + L1 + L2 (4 products) in ONE kernel, 1024 threads
// dynamic smem: sL1n [2][4096] | sL1t [2][64*68]
// ============================================================================
__global__ void __launch_bounds__(1024)
prep_kernel(const float* __restrict__ Tr,
            const float* __restrict__ Em,
            const float* __restrict__ Pi) {
    extern __shared__ float dynP[];
    float* sL1n = dynP;              // 8192 floats
    float* sL1t = dynP + 8192;       // 2 * 4352 floats (stride 68)

    __shared__ float rowm[NS], rowinv[NS];
    __shared__ float sE[2][NS];
    __shared__ float sred[32];
    __shared__ float sbcA[4];
    __shared__ int   seiA[4];

    const int tid  = threadIdx.x;
    const int lane = tid & 31;
    const int w    = tid >> 5;

    if (tid == 0) g_acc = 0.0;

    // --- T row-softmax params: warp w handles rows w and w+32 ---
#pragma unroll
    for (int rr = 0; rr < 2; rr++) {
        const int r = w + rr * 32;
        const float v0 = Tr[r * NS + lane];
        const float v1 = Tr[r * NS + lane + 32];
        float m = fmaxf(v0, v1);
#pragma unroll
        for (int off = 16; off > 0; off >>= 1)
            m = fmaxf(m, __shfl_xor_sync(0xffffffffu, m, off));
        const float e0 = expf(v0 - m), e1v = expf(v1 - m);
        float s = e0 + e1v;
#pragma unroll
        for (int off = 16; off > 0; off >>= 1)
            s += __shfl_xor_sync(0xffffffffu, s, off);
        if (lane == 0) { rowm[r] = m; rowinv[r] = 1.f / s; }
    }
    if (tid < NS) {
        const float a = Em[tid * 2 + 0], b2 = Em[tid * 2 + 1];
        const float mm = fmaxf(a, b2);
        const float ea = expf(a - mm), eb = expf(b2 - mm);
        const float is = 1.f / (ea + eb);
        sE[0][tid] = ea * is;  sE[1][tid] = eb * is;
        g_E0[tid] = ea * is;   g_E1[tid] = eb * is;
    }
    if (w == 1) {
        const float v0 = Pi[lane], v1 = Pi[lane + 32];
        float m = fmaxf(v0, v1);
#pragma unroll
        for (int off = 16; off > 0; off >>= 1)
            m = fmaxf(m, __shfl_xor_sync(0xffffffffu, m, off));
        const float e0 = expf(v0 - m), e1v = expf(v1 - m);
        float s = e0 + e1v;
#pragma unroll
        for (int off = 16; off > 0; off >>= 1)
            s += __shfl_xor_sync(0xffffffffu, s, off);
        const float inv = 1.f / s;
        g_Pi[lane] = e0 * inv;  g_Pi[lane + 32] = e1v * inv;
    }
    __syncthreads();

    // --- L1_y[k][o], normalized; write normal + transposed(pad 68) + global ---
    for (int y = 0; y < 2; y++) {
        float vv[4], vmax = 0.f;
#pragma unroll
        for (int i = 0; i < 4; i++) {
            const int idx = tid + i * 1024;
            const int k = idx >> 6, o = idx & 63;
            const float v = expf(Tr[idx] - rowm[k]) * rowinv[k] * sE[y][o];
            vv[i] = v; vmax = fmaxf(vmax, v);
        }
#pragma unroll
        for (int off = 16; off > 0; off >>= 1)
            vmax = fmaxf(vmax, __shfl_xor_sync(0xffffffffu, vmax, off));
        if (lane == 0) sred[w] = vmax;
        __syncthreads();
        if (tid < 32) {
            float m = sred[lane];
#pragma unroll
            for (int off = 16; off > 0; off >>= 1)
                m = fmaxf(m, __shfl_xor_sync(0xffffffffu, m, off));
            if (lane == 0) {
                const int e = (__float_as_int(m) >> 23) - 127;
                seiA[y] = e;  g_e1[y] = e;
                sbcA[y] = __int_as_float((127 - e) << 23);
            }
        }
        __syncthreads();
        const float sc = sbcA[y];
#pragma unroll
        for (int i = 0; i < 4; i++) {
            const int idx = tid + i * 1024;
            const int k = idx >> 6, o = idx & 63;
            const float v = vv[i] * sc;
            sL1n[y * 4096 + idx]         = v;
            sL1t[y * 4352 + o * 68 + k]  = v;
            g_L1[y * 4096 + idx]         = v;
        }
        __syncthreads();
    }

    // --- L2[g] = L1[g>>1] @ L1[g&1] : group g = tid>>8 (256 threads each) ---
    {
        const int g    = tid >> 8;
        const int gtid = tid & 255;
        const int j    = gtid & 63;
        const int h    = gtid >> 6;
        u64 acc[8];
        gemm16(sL1t + (g >> 1) * 4352, 68, sL1n + (g & 1) * 4096, j, h, acc);
        float out[16];
#pragma unroll
        for (int p = 0; p < 8; p++) upk2(acc[p], out[2 * p], out[2 * p + 1]);
        float mx = 0.f;
#pragma unroll
        for (int t = 0; t < 16; t++) mx = fmaxf(mx, out[t]);
#pragma unroll
        for (int off = 16; off > 0; off >>= 1)
            mx = fmaxf(mx, __shfl_xor_sync(0xffffffffu, mx, off));
        if (lane == 0) sred[w] = mx;
        __syncthreads();
        if (tid < 4) {
            float m = sred[8 * tid];
#pragma unroll
            for (int q = 1; q < 8; q++) m = fmaxf(m, sred[8 * tid + q]);
            const int e = (__float_as_int(m) >> 23) - 127;
            sbcA[tid] = __int_as_float((127 - e) << 23);
            g_e2[tid] = seiA[tid >> 1] + seiA[tid & 1] + e;
        }
        __syncthreads();
        const float sc = sbcA[g];
#pragma unroll
        for (int t = 0; t < 16; t++)
            g_L2[g * 4096 + (h * 16 + t) * NS + j] = out[t] * sc;
#pragma unroll
        for (int q = 0; q < 4; q++) {
            float4 wv = make_float4(out[4 * q] * sc, out[4 * q + 1] * sc,
                                    out[4 * q + 2] * sc, out[4 * q + 3] * sc);
            *(float4*)(g_L2t + g * 4096 + j * NS + h * 16 + 4 * q) = wv;
        }
    }
}

// ============================================================================
// combine: stage1: L4 = L2@L2 (grid16), stage2: L8t = L4@L4 (grid 256)
// ============================================================================
__global__ void __launch_bounds__(256) combine_kernel(int stage) {
    __shared__ float At[NS * NS];
    __shared__ float Bn[NS * NS];
    __shared__ float sred[8];
    __shared__ float sbc;
    __shared__ int   sei;

    const float *Asrc_t, *Bsrc; float *C, *Ct; const int *eA; int *eC; int bitsB;
    if (stage == 1) { Asrc_t = g_L2t; Bsrc = g_L2; C = g_L4;   Ct = g_L4t;
                      eA = g_e2; eC = g_e4; bitsB = 2; }
    else            { Asrc_t = g_L4t; Bsrc = g_L4; C = nullptr; Ct = g_L8t;
                      eA = g_e4; eC = g_e8; bitsB = 4; }

    const int c = blockIdx.x;
    const int a = c >> bitsB;
    const int b = c & ((1 << bitsB) - 1);
    const int tid  = threadIdx.x;
    const int lane = tid & 31;
    const int w    = tid >> 5;
    const int j = tid & 63;
    const int h = tid >> 6;

    {
        const float4* Ag = (const float4*)(Asrc_t + a * 4096);
        const float4* Bg = (const float4*)(Bsrc   + b * 4096);
        float4* As4 = (float4*)At; float4* Bs4 = (float4*)Bn;
#pragma unroll
        for (int i = 0; i < 4; i++) { As4[tid + 256 * i] = Ag[tid + 256 * i];
                                      Bs4[tid + 256 * i] = Bg[tid + 256 * i]; }
    }
    __syncthreads();

    u64 acc[8];
    gemm16(At, 64, Bn, j, h, acc);
    float out[16];
#pragma unroll
    for (int p = 0; p < 8; p++) upk2(acc[p], out[2 * p], out[2 * p + 1]);
    float mx = 0.f;
#pragma unroll
    for (int t = 0; t < 16; t++) mx = fmaxf(mx, out[t]);
#pragma unroll
    for (int off = 16; off > 0; off >>= 1)
        mx = fmaxf(mx, __shfl_xor_sync(0xffffffffu, mx, off));
    if (lane == 0) sred[w] = mx;
    __syncthreads();
    if (tid == 0) {
        float m = sred[0];
#pragma unroll
        for (int q = 1; q < 8; q++) m = fmaxf(m, sred[q]);
        const int e = (__float_as_int(m) >> 23) - 127;
        sbc = __int_as_float((127 - e) << 23);
        sei = e;
    }
    __syncthreads();
    const float sc = sbc;
    if (stage == 1) {
#pragma unroll
        for (int t = 0; t < 16; t++)
            C[c * 4096 + (h * 16 + t) * NS + j] = out[t] * sc;
    }
#pragma unroll
    for (int q = 0; q < 4; q++) {
        float4 wv = make_float4(out[4 * q] * sc, out[4 * q + 1] * sc,
                                out[4 * q + 2] * sc, out[4 * q + 3] * sc);
        *(float4*)(Ct + c * 4096 + j * NS + h * 16 + 4 * q) = wv;
    }
    if (tid == 0) eC[c] = eA[a] + eA[b] + sei;
}

// ============================================================================
// final: Tmp = L8[a]@L2[b] (transposed into smem), then codes 2*c2+d = Tmp@L1[d]
// dynamic smem: At 4096 | Bn 4096 | Ct 64*68 floats
// ============================================================================
__global__ void __launch_bounds__(256) final_kernel() {
    extern __shared__ float dynF[];
    float* At = dynF;
    float* Bn = dynF + 4096;
    float* Ct = dynF + 8192;      // stride 68

    __shared__ float sred[8];
    __shared__ float sbc;
    __shared__ int   sei;

    const int c2 = blockIdx.x;
    const int a  = c2 >> 2;
    const int b  = c2 & 3;
    const int tid  = threadIdx.x;
    const int lane = tid & 31;
    const int w    = tid >> 5;
    const int j = tid & 63;
    const int h = tid >> 6;

    {
        const float4* Ag = (const float4*)(g_L8t + a * 4096);
        const float4* Bg = (const float4*)(g_L2  + b * 4096);
        float4* As4 = (float4*)At; float4* Bs4 = (float4*)Bn;
#pragma unroll
        for (int i = 0; i < 4; i++) { As4[tid + 256 * i] = Ag[tid + 256 * i];
                                      Bs4[tid + 256 * i] = Bg[tid + 256 * i]; }
    }
    __syncthreads();

    // GEMM1: Tmp = L8 @ L2, stored transposed: Ct[j*68 + r] (values bounded)
    {
        u64 acc[8];
        gemm16(At, 64, Bn, j, h, acc);
#pragma unroll
        for (int p = 0; p < 8; p++)
            *(u64*)(Ct + j * 68 + h * 16 + 2 * p) = acc[p];
    }
    __syncthreads();

    const int eab = g_e8[a] + g_e2[b];

#pragma unroll
    for (int d = 0; d < 2; d++) {
        // stage L1[d] (normal) into Bn
        {
            const float4* Bg = (const float4*)(g_L1 + d * 4096);
            float4* Bs4 = (float4*)Bn;
#pragma unroll
            for (int i = 0; i < 4; i++) Bs4[tid + 256 * i] = Bg[tid + 256 * i];
        }
        __syncthreads();

        u64 acc[8];
        gemm16(Ct, 68, Bn, j, h, acc);
        float out[16];
#pragma unroll
        for (int p = 0; p < 8; p++) upk2(acc[p], out[2 * p], out[2 * p + 1]);
        float mx = 0.f;
#pragma unroll
        for (int t = 0; t < 16; t++) mx = fmaxf(mx, out[t]);
#pragma unroll
        for (int off = 16; off > 0; off >>= 1)
            mx = fmaxf(mx, __shfl_xor_sync(0xffffffffu, mx, off));
        if (lane == 0) sred[w] = mx;
        __syncthreads();
        if (tid == 0) {
            float m = sred[0];
#pragma unroll
            for (int q = 1; q < 8; q++) m = fmaxf(m, sred[q]);
            const int e = (__float_as_int(m) >> 23) - 127;
            sbc = __int_as_float((127 - e) << 23);
            sei = e;
        }
        __syncthreads();
        const float sc = sbc;
        const int code = c2 * 2 + d;

        unsigned wd[4];
#pragma unroll
        for (int q = 0; q < 4; q++) {
            const int t = 4 * q;
            const unsigned p01 = f2_e4m3x2(out[t + 1] * sc, out[t + 0] * sc);
            const unsigned p23 = f2_e4m3x2(out[t + 3] * sc, out[t + 2] * sc);
            wd[q] = p01 | (p23 << 16);
        }
        uint4* dst = (uint4*)((char*)g_Pt4 + (size_t)code * 4096
                              + ((j < 32 ? 0 : 4) + h) * 512 + (j & 31) * 16);
        *dst = make_uint4(wd[0], wd[1], wd[2], wd[3]);
        if (tid == 0) g_e11[code] = eab + g_e1[d] + sei;
        __syncthreads();   // before Bn overwrite next d
    }
}

// ============================================================================
// main: one warp per element; inline ballot codes; fp8 table, half2 matvec
// ============================================================================
#define PREFETCH(MB, c)                                                       \
    {                                                                         \
        const uint4* __restrict__ tp = g_Pt4 + (size_t)(c) * 256 + lane;      \
        _Pragma("unroll")                                                     \
        for (int i = 0; i < 8; i++) MB[i] = tp[i * 32];                       \
    }

#define PROC8(u, av0, av1, acc)                                               \
    acc = __hfma2(e4m3x2_h2((unsigned short)(u).x),         as_h2((av0).x), acc); \
    acc = __hfma2(e4m3x2_h2((unsigned short)((u).x >> 16)), as_h2((av0).y), acc); \
    acc = __hfma2(e4m3x2_h2((unsigned short)(u).y),         as_h2((av0).z), acc); \
    acc = __hfma2(e4m3x2_h2((unsigned short)((u).y >> 16)), as_h2((av0).w), acc); \
    acc = __hfma2(e4m3x2_h2((unsigned short)(u).z),         as_h2((av1).x), acc); \
    acc = __hfma2(e4m3x2_h2((unsigned short)((u).z >> 16)), as_h2((av1).y), acc); \
    acc = __hfma2(e4m3x2_h2((unsigned short)(u).w),         as_h2((av1).z), acc); \
    acc = __hfma2(e4m3x2_h2((unsigned short)((u).w >> 16)), as_h2((av1).w), acc);

#define PACKSTORE(PP)                                                         \
    {                                                                         \
        const float ev = __shfl_sync(0xffffffffu, s_lo, 0);                   \
        int e = (__float_as_int(ev) >> 23) - 125;                             \
        e = max(-120, min(120, e));                                           \
        const float rsc = __int_as_float((127 - e) << 23);                    \
        s_lo *= rsc; s_hi *= rsc; ce += e;                                    \
        const float lo0 = __shfl_sync(0xffffffffu, s_lo, (2 * lane) & 31);    \
        const float lo1 = __shfl_sync(0xffffffffu, s_lo, (2 * lane + 1) & 31);\
        const float hi0 = __shfl_sync(0xffffffffu, s_hi, (2 * lane) & 31);    \
        const float hi1 = __shfl_sync(0xffffffffu, s_hi, (2 * lane + 1) & 31);\
        const float x0 = lane < 16 ? lo0 : hi0;                               \
        const float x1 = lane < 16 ? lo1 : hi1;                               \
        s_ah[wid][PP][lane] = __floats2half2_rn(x0, x1);                      \
        __syncwarp();                                                         \
    }

#define COMPUTE(MB, CODE)                                                     \
    {                                                                         \
        const uint4* __restrict__ ah = (const uint4*)s_ah[wid][p];            \
        uint4 au[8];                                                          \
        _Pragma("unroll")                                                     \
        for (int q = 0; q < 8; q++) au[q] = ah[q];                            \
        __half2 c0 = __float2half2_rn(0.f), c1 = c0, c2 = c0, c3 = c0;        \
        __half2 d0 = c0, d1 = c0, d2 = c0, d3 = c0;                           \
        PROC8(MB[0], au[0], au[1], c0)                                        \
        PROC8(MB[1], au[2], au[3], c1)                                        \
        PROC8(MB[2], au[4], au[5], c2)                                        \
        PROC8(MB[3], au[6], au[7], c3)                                        \
        PROC8(MB[4], au[0], au[1], d0)                                        \
        PROC8(MB[5], au[2], au[3], d1)                                        \
        PROC8(MB[6], au[4], au[5], d2)                                        \
        PROC8(MB[7], au[6], au[7], d3)                                        \
        const __half2 tc = __hadd2(__hadd2(c0, c1), __hadd2(c2, c3));         \
        const __half2 td = __hadd2(__hadd2(d0, d1), __hadd2(d2, d3));         \
        s_lo = __low2float(tc) + __high2float(tc);                            \
        s_hi = __low2float(td) + __high2float(td);                            \
        ce += g_e11[CODE];                                                    \
        p ^= 1;                                                               \
        PACKSTORE(p)                                                          \
    }

__device__ __forceinline__ int getcode(const unsigned* __restrict__ bw, int j) {
    const int base = 1 + LBLK * j;
    const unsigned lo = bw[base >> 5];
    const unsigned hi = bw[(base >> 5) + 1];
    return (int)(__brev(__funnelshift_r(lo, hi, base & 31)) >> 21);
}

__global__ void __launch_bounds__(128)
hmm_main_kernel(const int* __restrict__ y) {
    __shared__ __align__(16) __half2 s_ah[4][2][32];
    __shared__ unsigned s_bw[4][34];

    const int tid  = threadIdx.x;
    const int lane = tid & 31;
    const int wid  = tid >> 5;
    const int b    = blockIdx.x * 4 + wid;
    const int* __restrict__ yrow = y + b * DIM;

#pragma unroll
    for (int ch = 0; ch < 32; ch++) {
        const unsigned w = __ballot_sync(0xffffffffu, yrow[ch * 32 + lane]);
        if (lane == 0) s_bw[wid][ch] = w;
    }
    if (lane == 0) { s_bw[wid][32] = 0u; s_bw[wid][33] = 0u; }
    __syncwarp();
    const unsigned* __restrict__ bw = s_bw[wid];

    const int y0 = (int)(bw[0] & 1u);
    float s_lo = g_Pi[lane]      * (y0 ? g_E1[lane]      : g_E0[lane]);
    float s_hi = g_Pi[lane + 32] * (y0 ? g_E1[lane + 32] : g_E0[lane + 32]);

    int ce = 0, p = 0;
    PACKSTORE(0)

    uint4 mA[8], mB[8];
    int cA = getcode(bw, 0), cB;
    PREFETCH(mA, cA)

    for (int jj = 0; jj < 92; jj += 2) {
        cB = getcode(bw, jj + 1);
        PREFETCH(mB, cB)
        COMPUTE(mA, cA)
        cA = getcode(bw, jj + 2);
        PREFETCH(mA, cA)
        COMPUTE(mB, cB)
    }
    COMPUTE(mA, cA)   // j = 92 (prefetched at jj = 90)

    float v = s_lo + s_hi;
#pragma unroll
    for (int off = 16; off > 0; off >>= 1)
        v += __shfl_xor_sync(0xffffffffu, v, off);

    if (lane == 0) {
        const double logp = (double)logf(v) + (double)ce * 0.6931471805599453;
        atomicAdd(&g_acc, logp);
    }
}

__global__ void fin_kernel(float* out) {
    out[0] = (float)(g_acc * (1.0 / 4096.0));
}

extern "C" void kernel_launch(void* const* d_in, const int* in_sizes, int n_in,
                              void* d_out, int out_size) {
    const int*   y  = (const int*)  d_in[0];
    const float* Tr = (const float*)d_in[1];
    const float* Em = (const float*)d_in[2];
    const float* Pi = (const float*)d_in[3];

    cudaFuncSetAttribute(prep_kernel,
        cudaFuncAttributeMaxDynamicSharedMemorySize, 67584);
    cudaFuncSetAttribute(final_kernel,
        cudaFuncAttributeMaxDynamicSharedMemorySize, 50176);

    prep_kernel<<<1, 1024, 67584>>>(Tr, Em, Pi);
    combine_kernel<<<16, 256>>>(1);     // L4 (+L4t)
    combine_kernel<<<256, 256>>>(2);    // L8t
    final_kernel<<<1024, 256, 50176>>>();
    hmm_main_kernel<<<BATCH / 4, 128>>>(y);
    fin_kernel<<<1, 1>>>((float*)d_out);
}

// round 9
// speedup vs baseline: 1.4669x; 1.1121x over previous
#include <cuda_runtime.h>
#include <cuda_bf16.h>
#include <cuda_fp16.h>

#define BATCH 4096
#define DIM   1024
#define NS    64
#define LBLK  11
#define NCODE 2048

typedef unsigned long long u64;

// ---- device-global scratch (static; no runtime alloc) ----
__device__ float  g_E0[NS], g_E1[NS], g_Pi[NS];
__device__ float  g_L1[2 * NS * NS];                  // normal [k][o]
__device__ float  g_L2[4 * NS * NS],  g_L2t[4 * NS * NS];
__device__ float  g_L4[16 * NS * NS], g_L4t[16 * NS * NS];
__device__ float  g_L8t[256 * NS * NS];               // only transposed needed
__device__ int    g_e1[2], g_e2[4], g_e4[16], g_e8[256], g_e11[NCODE];
// fp8 e4m3 table, permuted: byte(c,o,k) = c*4096 + ((o<32?0:4)+(k>>4))*512 + (o&31)*16 + (k&15)
__device__ uint4  g_Pt4[NCODE * 256];    // 8 MB
__device__ double g_acc;
__device__ unsigned g_done;

// ---- packed helpers ----
__device__ __forceinline__ u64 pk2(float lo, float hi) {
    u64 r; asm("mov.b64 %0, {%1,%2};" : "=l"(r) : "f"(lo), "f"(hi)); return r;
}
__device__ __forceinline__ void upk2(u64 v, float &lo, float &hi) {
    asm("mov.b64 {%0,%1}, %2;" : "=f"(lo), "=f"(hi) : "l"(v));
}
__device__ __forceinline__ u64 fma2(u64 a, u64 b, u64 c) {
    u64 d; asm("fma.rn.f32x2 %0, %1, %2, %3;" : "=l"(d) : "l"(a), "l"(b), "l"(c)); return d;
}
__device__ __forceinline__ unsigned short f2_e4m3x2(float hi, float lo) {
    unsigned short r;
    asm("cvt.rn.satfinite.e4m3x2.f32 %0, %1, %2;" : "=h"(r) : "f"(hi), "f"(lo));
    return r;
}
__device__ __forceinline__ __half2 e4m3x2_h2(unsigned short s) {
    unsigned r;
    asm("cvt.rn.f16x2.e4m3x2 %0, %1;" : "=r"(r) : "h"(s));
    return *(__half2*)&r;
}
__device__ __forceinline__ __half2 as_h2(unsigned w) { return *(__half2*)&w; }

// ---- 4x4-tile GEMM fragment ----
// thread (jc, rc): rows 4rc..4rc+3, cols 4jc..4jc+3
// At: transposed A in smem, At[k*strideF + r] = A[r][k] (strideF*4 mult of 16)
// B : normal smem [k*64 + j].  out[r][c] = sum_k A[4rc+r][k] * B[k][4jc+c]
__device__ __forceinline__ void gemm4x4(const float* __restrict__ At, int strideF,
                                        const float* __restrict__ B,
                                        int jc, int rc, float out[4][4]) {
    u64 acc[4][2];
#pragma unroll
    for (int r = 0; r < 4; r++) { acc[r][0] = 0ull; acc[r][1] = 0ull; }
#pragma unroll 16
    for (int k = 0; k < NS; k++) {
        const float4 av = *(const float4*)(At + k * strideF + 4 * rc);
        const float4 bv = *(const float4*)(B  + k * NS      + 4 * jc);
        const u64 c01 = ((const u64*)&bv)[0];
        const u64 c23 = ((const u64*)&bv)[1];
        const u64 a0 = pk2(av.x, av.x), a1 = pk2(av.y, av.y);
        const u64 a2 = pk2(av.z, av.z), a3 = pk2(av.w, av.w);
        acc[0][0] = fma2(c01, a0, acc[0][0]); acc[0][1] = fma2(c23, a0, acc[0][1]);
        acc[1][0] = fma2(c01, a1, acc[1][0]); acc[1][1] = fma2(c23, a1, acc[1][1]);
        acc[2][0] = fma2(c01, a2, acc[2][0]); acc[2][1] = fma2(c23, a2, acc[2][1]);
        acc[3][0] = fma2(c01, a3, acc[3][0]); acc[3][1] = fma2(c23, a3, acc[3][1]);
    }
#pragma unroll
    for (int r = 0; r < 4; r++) {
        upk2(acc[r][0], out[r][0], out[r][1]);
        upk2(acc[r][1], out[r][2], out[r][3]);
    }
}

// ============================================================================
// prep: softmaxes + L1 + L2 (4 products) in ONE kernel, 1024 threads
// dynamic smem: sL1n [2][4096] | sL1t [2][64*68]
// ============================================================================
__global__ void __launch_bounds__(1024)
prep_kernel(const float* __restrict__ Tr,
            const float* __restrict__ Em,
            const float* __restrict__ Pi) {
    extern __shared__ float dynP[];
    float* sL1n = dynP;              // 8192 floats
    float* sL1t = dynP + 8192;       // 2 * 4352 floats (stride 68)

    __shared__ float rowm[NS], rowinv[NS];
    __shared__ float sE[2][NS];
    __shared__ float sred[32];
    __shared__ float sbcA[4];
    __shared__ int   seiA[4];

    const int tid  = threadIdx.x;
    const int lane = tid & 31;
    const int w    = tid >> 5;

    if (tid == 0) { g_acc = 0.0; g_done = 0u; }

    // --- T row-softmax params: warp w handles rows w and w+32 ---
#pragma unroll
    for (int rr = 0; rr < 2; rr++) {
        const int r = w + rr * 32;
        const float v0 = Tr[r * NS + lane];
        const float v1 = Tr[r * NS + lane + 32];
        float m = fmaxf(v0, v1);
#pragma unroll
        for (int off = 16; off > 0; off >>= 1)
            m = fmaxf(m, __shfl_xor_sync(0xffffffffu, m, off));
        const float e0 = expf(v0 - m), e1v = expf(v1 - m);
        float s = e0 + e1v;
#pragma unroll
        for (int off = 16; off > 0; off >>= 1)
            s += __shfl_xor_sync(0xffffffffu, s, off);
        if (lane == 0) { rowm[r] = m; rowinv[r] = 1.f / s; }
    }
    if (tid < NS) {
        const float a = Em[tid * 2 + 0], b2 = Em[tid * 2 + 1];
        const float mm = fmaxf(a, b2);
        const float ea = expf(a - mm), eb = expf(b2 - mm);
        const float is = 1.f / (ea + eb);
        sE[0][tid] = ea * is;  sE[1][tid] = eb * is;
        g_E0[tid] = ea * is;   g_E1[tid] = eb * is;
    }
    if (w == 1) {
        const float v0 = Pi[lane], v1 = Pi[lane + 32];
        float m = fmaxf(v0, v1);
#pragma unroll
        for (int off = 16; off > 0; off >>= 1)
            m = fmaxf(m, __shfl_xor_sync(0xffffffffu, m, off));
        const float e0 = expf(v0 - m), e1v = expf(v1 - m);
        float s = e0 + e1v;
#pragma unroll
        for (int off = 16; off > 0; off >>= 1)
            s += __shfl_xor_sync(0xffffffffu, s, off);
        const float inv = 1.f / s;
        g_Pi[lane] = e0 * inv;  g_Pi[lane + 32] = e1v * inv;
    }
    __syncthreads();

    // --- L1_y[k][o], normalized; write normal + transposed(pad 68) + global ---
    for (int y = 0; y < 2; y++) {
        float vv[4], vmax = 0.f;
#pragma unroll
        for (int i = 0; i < 4; i++) {
            const int idx = tid + i * 1024;
            const int k = idx >> 6, o = idx & 63;
            const float v = expf(Tr[idx] - rowm[k]) * rowinv[k] * sE[y][o];
            vv[i] = v; vmax = fmaxf(vmax, v);
        }
#pragma unroll
        for (int off = 16; off > 0; off >>= 1)
            vmax = fmaxf(vmax, __shfl_xor_sync(0xffffffffu, vmax, off));
        if (lane == 0) sred[w] = vmax;
        __syncthreads();
        if (tid < 32) {
            float m = sred[lane];
#pragma unroll
            for (int off = 16; off > 0; off >>= 1)
                m = fmaxf(m, __shfl_xor_sync(0xffffffffu, m, off));
            if (lane == 0) {
                const int e = (__float_as_int(m) >> 23) - 127;
                seiA[y] = e;  g_e1[y] = e;
                sbcA[y] = __int_as_float((127 - e) << 23);
            }
        }
        __syncthreads();
        const float sc = sbcA[y];
#pragma unroll
        for (int i = 0; i < 4; i++) {
            const int idx = tid + i * 1024;
            const int k = idx >> 6, o = idx & 63;
            const float v = vv[i] * sc;
            sL1n[y * 4096 + idx]         = v;
            sL1t[y * 4352 + o * 68 + k]  = v;
            g_L1[y * 4096 + idx]         = v;
        }
        __syncthreads();
    }

    // --- L2[g] = L1[g>>1] @ L1[g&1] : group g = tid>>8 (256 threads each) ---
    {
        const int g    = tid >> 8;
        const int gtid = tid & 255;
        const int jc   = gtid & 15;
        const int rc   = gtid >> 4;
        float out[4][4];
        gemm4x4(sL1t + (g >> 1) * 4352, 68, sL1n + (g & 1) * 4096, jc, rc, out);
        float mx = 0.f;
#pragma unroll
        for (int r = 0; r < 4; r++)
#pragma unroll
            for (int c = 0; c < 4; c++) mx = fmaxf(mx, out[r][c]);
#pragma unroll
        for (int off = 16; off > 0; off >>= 1)
            mx = fmaxf(mx, __shfl_xor_sync(0xffffffffu, mx, off));
        if (lane == 0) sred[w] = mx;
        __syncthreads();
        if (tid < 4) {
            float m = sred[8 * tid];
#pragma unroll
            for (int q = 1; q < 8; q++) m = fmaxf(m, sred[8 * tid + q]);
            const int e = (__float_as_int(m) >> 23) - 127;
            sbcA[tid] = __int_as_float((127 - e) << 23);
            g_e2[tid] = seiA[tid >> 1] + seiA[tid & 1] + e;
        }
        __syncthreads();
        const float sc = sbcA[g];
#pragma unroll
        for (int r = 0; r < 4; r++) {
            float4 wv = make_float4(out[r][0] * sc, out[r][1] * sc,
                                    out[r][2] * sc, out[r][3] * sc);
            *(float4*)(g_L2 + g * 4096 + (4 * rc + r) * NS + 4 * jc) = wv;
        }
#pragma unroll
        for (int c = 0; c < 4; c++) {
            float4 wv = make_float4(out[0][c] * sc, out[1][c] * sc,
                                    out[2][c] * sc, out[3][c] * sc);
            *(float4*)(g_L2t + g * 4096 + (4 * jc + c) * NS + 4 * rc) = wv;
        }
    }
}

// ============================================================================
// combine: stage1: L4 = L2@L2 (grid16), stage2: L8t = L4@L4 (grid 256)
// ============================================================================
__global__ void __launch_bounds__(256) combine_kernel(int stage) {
    __shared__ float At[NS * NS];
    __shared__ float Bn[NS * NS];
    __shared__ float sred[8];
    __shared__ float sbc;
    __shared__ int   sei;

    const float *Asrc_t, *Bsrc; float *C, *Ct; const int *eA; int *eC; int bitsB;
    if (stage == 1) { Asrc_t = g_L2t; Bsrc = g_L2; C = g_L4;   Ct = g_L4t;
                      eA = g_e2; eC = g_e4; bitsB = 2; }
    else            { Asrc_t = g_L4t; Bsrc = g_L4; C = nullptr; Ct = g_L8t;
                      eA = g_e4; eC = g_e8; bitsB = 4; }

    const int c = blockIdx.x;
    const int a = c >> bitsB;
    const int b = c & ((1 << bitsB) - 1);
    const int tid  = threadIdx.x;
    const int lane = tid & 31;
    const int w    = tid >> 5;
    const int jc   = tid & 15;
    const int rc   = tid >> 4;

    {
        const float4* Ag = (const float4*)(Asrc_t + a * 4096);
        const float4* Bg = (const float4*)(Bsrc   + b * 4096);
        float4* As4 = (float4*)At; float4* Bs4 = (float4*)Bn;
#pragma unroll
        for (int i = 0; i < 4; i++) { As4[tid + 256 * i] = Ag[tid + 256 * i];
                                      Bs4[tid + 256 * i] = Bg[tid + 256 * i]; }
    }
    __syncthreads();

    float out[4][4];
    gemm4x4(At, 64, Bn, jc, rc, out);
    float mx = 0.f;
#pragma unroll
    for (int r = 0; r < 4; r++)
#pragma unroll
        for (int cc = 0; cc < 4; cc++) mx = fmaxf(mx, out[r][cc]);
#pragma unroll
    for (int off = 16; off > 0; off >>= 1)
        mx = fmaxf(mx, __shfl_xor_sync(0xffffffffu, mx, off));
    if (lane == 0) sred[w] = mx;
    __syncthreads();
    if (tid == 0) {
        float m = sred[0];
#pragma unroll
        for (int q = 1; q < 8; q++) m = fmaxf(m, sred[q]);
        const int e = (__float_as_int(m) >> 23) - 127;
        sbc = __int_as_float((127 - e) << 23);
        sei = e;
    }
    __syncthreads();
    const float sc = sbc;
    if (stage == 1) {
#pragma unroll
        for (int r = 0; r < 4; r++) {
            float4 wv = make_float4(out[r][0] * sc, out[r][1] * sc,
                                    out[r][2] * sc, out[r][3] * sc);
            *(float4*)(C + c * 4096 + (4 * rc + r) * NS + 4 * jc) = wv;
        }
    }
#pragma unroll
    for (int cc = 0; cc < 4; cc++) {
        float4 wv = make_float4(out[0][cc] * sc, out[1][cc] * sc,
                                out[2][cc] * sc, out[3][cc] * sc);
        *(float4*)(Ct + c * 4096 + (4 * jc + cc) * NS + 4 * rc) = wv;
    }
    if (tid == 0) eC[c] = eA[a] + eA[b] + sei;
}

// ============================================================================
// final: Tmp = L8[a]@L2[b] (transposed into smem), then codes 2*c2+d = Tmp@L1[d]
// dynamic smem: At 4096 | Bn 4096 | Ct 64*68 floats
// ============================================================================
__global__ void __launch_bounds__(256) final_kernel() {
    extern __shared__ float dynF[];
    float* At = dynF;
    float* Bn = dynF + 4096;
    float* Ct = dynF + 8192;      // stride 68

    __shared__ float sred[8];
    __shared__ float sbc;
    __shared__ int   sei;

    const int c2 = blockIdx.x;
    const int a  = c2 >> 2;
    const int b  = c2 & 3;
    const int tid  = threadIdx.x;
    const int lane = tid & 31;
    const int w    = tid >> 5;
    const int jc   = tid & 15;
    const int rc   = tid >> 4;

    {
        const float4* Ag = (const float4*)(g_L8t + a * 4096);
        const float4* Bg = (const float4*)(g_L2  + b * 4096);
        float4* As4 = (float4*)At; float4* Bs4 = (float4*)Bn;
#pragma unroll
        for (int i = 0; i < 4; i++) { As4[tid + 256 * i] = Ag[tid + 256 * i];
                                      Bs4[tid + 256 * i] = Bg[tid + 256 * i]; }
    }
    __syncthreads();

    // GEMM1: Tmp = L8 @ L2, stored transposed: Ct[j*68 + r] (values bounded)
    {
        float out[4][4];
        gemm4x4(At, 64, Bn, jc, rc, out);
#pragma unroll
        for (int cc = 0; cc < 4; cc++) {
            float4 wv = make_float4(out[0][cc], out[1][cc], out[2][cc], out[3][cc]);
            *(float4*)(Ct + (4 * jc + cc) * 68 + 4 * rc) = wv;
        }
    }
    __syncthreads();

    const int eab = g_e8[a] + g_e2[b];

#pragma unroll
    for (int d = 0; d < 2; d++) {
        // stage L1[d] (normal) into Bn
        {
            const float4* Bg = (const float4*)(g_L1 + d * 4096);
            float4* Bs4 = (float4*)Bn;
#pragma unroll
            for (int i = 0; i < 4; i++) Bs4[tid + 256 * i] = Bg[tid + 256 * i];
        }
        __syncthreads();

        // out[r][c]: table row k = 4rc+r (input state), col o = 4jc+c
        float out[4][4];
        gemm4x4(Ct, 68, Bn, jc, rc, out);
        float mx = 0.f;
#pragma unroll
        for (int r = 0; r < 4; r++)
#pragma unroll
            for (int cc = 0; cc < 4; cc++) mx = fmaxf(mx, out[r][cc]);
#pragma unroll
        for (int off = 16; off > 0; off >>= 1)
            mx = fmaxf(mx, __shfl_xor_sync(0xffffffffu, mx, off));
        if (lane == 0) sred[w] = mx;
        __syncthreads();
        if (tid == 0) {
            float m = sred[0];
#pragma unroll
            for (int q = 1; q < 8; q++) m = fmaxf(m, sred[q]);
            const int e = (__float_as_int(m) >> 23) - 127;
            sbc = __int_as_float((127 - e) << 23);
            sei = e;
        }
        __syncthreads();
        const float sc = sbc;
        const int code = c2 * 2 + d;

        // e4m3 write: per col o = 4jc+cc, 4 consecutive k = 4rc..4rc+3 -> one u32
        const int k0 = 4 * rc;
#pragma unroll
        for (int cc = 0; cc < 4; cc++) {
            const int o = 4 * jc + cc;
            const unsigned p01 = f2_e4m3x2(out[1][cc] * sc, out[0][cc] * sc);
            const unsigned p23 = f2_e4m3x2(out[3][cc] * sc, out[2][cc] * sc);
            unsigned* dst = (unsigned*)((char*)g_Pt4 + (size_t)code * 4096
                            + ((o < 32 ? 0 : 4) + (k0 >> 4)) * 512
                            + (o & 31) * 16 + (k0 & 15));
            *dst = p01 | (p23 << 16);
        }
        if (tid == 0) g_e11[code] = eab + g_e1[d] + sei;
        __syncthreads();   // before Bn overwrite next d
    }
}

// ============================================================================
// main: one warp per element; inline ballot codes; fp8 table, half2 matvec
// ============================================================================
#define PREFETCH(MB, c)                                                       \
    {                                                                         \
        const uint4* __restrict__ tp = g_Pt4 + (size_t)(c) * 256 + lane;      \
        _Pragma("unroll")                                                     \
        for (int i = 0; i < 8; i++) MB[i] = tp[i * 32];                       \
    }

#define PROC8(u, av0, av1, acc)                                               \
    acc = __hfma2(e4m3x2_h2((unsigned short)(u).x),         as_h2((av0).x), acc); \
    acc = __hfma2(e4m3x2_h2((unsigned short)((u).x >> 16)), as_h2((av0).y), acc); \
    acc = __hfma2(e4m3x2_h2((unsigned short)(u).y),         as_h2((av0).z), acc); \
    acc = __hfma2(e4m3x2_h2((unsigned short)((u).y >> 16)), as_h2((av0).w), acc); \
    acc = __hfma2(e4m3x2_h2((unsigned short)(u).z),         as_h2((av1).x), acc); \
    acc = __hfma2(e4m3x2_h2((unsigned short)((u).z >> 16)), as_h2((av1).y), acc); \
    acc = __hfma2(e4m3x2_h2((unsigned short)(u).w),         as_h2((av1).z), acc); \
    acc = __hfma2(e4m3x2_h2((unsigned short)((u).w >> 16)), as_h2((av1).w), acc);

#define PACKSTORE(PP)                                                         \
    {                                                                         \
        const float ev = __shfl_sync(0xffffffffu, s_lo, 0);                   \
        int e = (__float_as_int(ev) >> 23) - 125;                             \
        e = max(-120, min(120, e));                                           \
        const float rsc = __int_as_float((127 - e) << 23);                    \
        s_lo *= rsc; s_hi *= rsc; ce += e;                                    \
        const float lo0 = __shfl_sync(0xffffffffu, s_lo, (2 * lane) & 31);    \
        const float lo1 = __shfl_sync(0xffffffffu, s_lo, (2 * lane + 1) & 31);\
        const float hi0 = __shfl_sync(0xffffffffu, s_hi, (2 * lane) & 31);    \
        const float hi1 = __shfl_sync(0xffffffffu, s_hi, (2 * lane + 1) & 31);\
        const float x0 = lane < 16 ? lo0 : hi0;                               \
        const float x1 = lane < 16 ? lo1 : hi1;                               \
        s_ah[wid][PP][lane] = __floats2half2_rn(x0, x1);                      \
        __syncwarp();                                                         \
    }

#define COMPUTE(MB, CODE)                                                     \
    {                                                                         \
        const uint4* __restrict__ ah = (const uint4*)s_ah[wid][p];            \
        uint4 au[8];                                                          \
        _Pragma("unroll")                                                     \
        for (int q = 0; q < 8; q++) au[q] = ah[q];                            \
        __half2 c0 = __float2half2_rn(0.f), c1 = c0, c2 = c0, c3 = c0;        \
        __half2 d0 = c0, d1 = c0, d2 = c0, d3 = c0;                           \
        PROC8(MB[0], au[0], au[1], c0)                                        \
        PROC8(MB[1], au[2], au[3], c1)                                        \
        PROC8(MB[2], au[4], au[5], c2)                                        \
        PROC8(MB[3], au[6], au[7], c3)                                        \
        PROC8(MB[4], au[0], au[1], d0)                                        \
        PROC8(MB[5], au[2], au[3], d1)                                        \
        PROC8(MB[6], au[4], au[5], d2)                                        \
        PROC8(MB[7], au[6], au[7], d3)                                        \
        const __half2 tc = __hadd2(__hadd2(c0, c1), __hadd2(c2, c3));         \
        const __half2 td = __hadd2(__hadd2(d0, d1), __hadd2(d2, d3));         \
        s_lo = __low2float(tc) + __high2float(tc);                            \
        s_hi = __low2float(td) + __high2float(td);                            \
        ce += g_e11[CODE];                                                    \
        p ^= 1;                                                               \
        PACKSTORE(p)                                                          \
    }

__device__ __forceinline__ int getcode(const unsigned* __restrict__ bw, int j) {
    const int base = 1 + LBLK * j;
    const unsigned lo = bw[base >> 5];
    const unsigned hi = bw[(base >> 5) + 1];
    return (int)(__brev(__funnelshift_r(lo, hi, base & 31)) >> 21);
}

__global__ void __launch_bounds__(128)
hmm_main_kernel(const int* __restrict__ y, float* __restrict__ outp) {
    __shared__ __align__(16) __half2 s_ah[4][2][32];
    __shared__ unsigned s_bw[4][34];

    const int tid  = threadIdx.x;
    const int lane = tid & 31;
    const int wid  = tid >> 5;
    const int b    = blockIdx.x * 4 + wid;
    const int* __restrict__ yrow = y + b * DIM;

#pragma unroll
    for (int ch = 0; ch < 32; ch++) {
        const unsigned w = __ballot_sync(0xffffffffu, yrow[ch * 32 + lane]);
        if (lane == 0) s_bw[wid][ch] = w;
    }
    if (lane == 0) { s_bw[wid][32] = 0u; s_bw[wid][33] = 0u; }
    __syncwarp();
    const unsigned* __restrict__ bw = s_bw[wid];

    const int y0 = (int)(bw[0] & 1u);
    float s_lo = g_Pi[lane]      * (y0 ? g_E1[lane]      : g_E0[lane]);
    float s_hi = g_Pi[lane + 32] * (y0 ? g_E1[lane + 32] : g_E0[lane + 32]);

    int ce = 0, p = 0;
    PACKSTORE(0)

    uint4 mA[8], mB[8];
    int cA = getcode(bw, 0), cB;
    PREFETCH(mA, cA)

    for (int jj = 0; jj < 92; jj += 2) {
        cB = getcode(bw, jj + 1);
        PREFETCH(mB, cB)
        COMPUTE(mA, cA)
        cA = getcode(bw, jj + 2);
        PREFETCH(mA, cA)
        COMPUTE(mB, cB)
    }
    COMPUTE(mA, cA)   // j = 92 (prefetched at jj = 90)

    float v = s_lo + s_hi;
#pragma unroll
    for (int off = 16; off > 0; off >>= 1)
        v += __shfl_xor_sync(0xffffffffu, v, off);

    if (lane == 0) {
        const double logp = (double)logf(v) + (double)ce * 0.6931471805599453;
        atomicAdd(&g_acc, logp);
        __threadfence();
        const unsigned done = atomicAdd(&g_done, 1u);
        if (done == (unsigned)(BATCH - 1)) {
            outp[0] = (float)(g_acc * (1.0 / 4096.0));
        }
    }
}

extern "C" void kernel_launch(void* const* d_in, const int* in_sizes, int n_in,
                              void* d_out, int out_size) {
    const int*   y  = (const int*)  d_in[0];
    const float* Tr = (const float*)d_in[1];
    const float* Em = (const float*)d_in[2];
    const float* Pi = (const float*)d_in[3];

    cudaFuncSetAttribute(prep_kernel,
        cudaFuncAttributeMaxDynamicSharedMemorySize, 67584);
    cudaFuncSetAttribute(final_kernel,
        cudaFuncAttributeMaxDynamicSharedMemorySize, 50176);

    prep_kernel<<<1, 1024, 67584>>>(Tr, Em, Pi);
    combine_kernel<<<16, 256>>>(1);     // L4 (+L4t)
    combine_kernel<<<256, 256>>>(2);    // L8t
    final_kernel<<<1024, 256, 50176>>>();
    hmm_main_kernel<<<BATCH / 4, 128>>>(y, (float*)d_out);
}

// round 10
// speedup vs baseline: 1.4831x; 1.0111x over previous
#include <cuda_runtime.h>
#include <cuda_bf16.h>
#include <cuda_fp16.h>

#define BATCH 4096
#define DIM   1024
#define NS    64
#define LBLK  11
#define NCODE 2048

typedef unsigned long long u64;

// ---- device-global scratch (static; no runtime alloc) ----
__device__ float  g_E0[NS], g_E1[NS], g_Pi[NS];
__device__ float  g_L1[2 * NS * NS];                  // normal [k][o]
__device__ float  g_L2[4 * NS * NS],  g_L2t[4 * NS * NS];
__device__ float  g_L3[8 * NS * NS];                  // L3[v] = L2[v>>1] @ L1[v&1]
__device__ float  g_L4[16 * NS * NS], g_L4t[16 * NS * NS];
__device__ float  g_L8t[256 * NS * NS];               // only transposed needed
__device__ int    g_e1[2], g_e2[4], g_e3[8], g_e4[16], g_e8[256], g_e11[NCODE];
// fp8 e4m3 table, permuted: byte(c,o,k) = c*4096 + ((o<32?0:4)+(k>>4))*512 + (o&31)*16 + (k&15)
__device__ uint4  g_Pt4[NCODE * 256];    // 8 MB
__device__ double g_acc;
__device__ unsigned g_done;

// ---- packed helpers ----
__device__ __forceinline__ u64 pk2(float lo, float hi) {
    u64 r; asm("mov.b64 %0, {%1,%2};" : "=l"(r) : "f"(lo), "f"(hi)); return r;
}
__device__ __forceinline__ void upk2(u64 v, float &lo, float &hi) {
    asm("mov.b64 {%0,%1}, %2;" : "=f"(lo), "=f"(hi) : "l"(v));
}
__device__ __forceinline__ u64 fma2(u64 a, u64 b, u64 c) {
    u64 d; asm("fma.rn.f32x2 %0, %1, %2, %3;" : "=l"(d) : "l"(a), "l"(b), "l"(c)); return d;
}
__device__ __forceinline__ unsigned short f2_e4m3x2(float hi, float lo) {
    unsigned short r;
    asm("cvt.rn.satfinite.e4m3x2.f32 %0, %1, %2;" : "=h"(r) : "f"(hi), "f"(lo));
    return r;
}
__device__ __forceinline__ __half2 e4m3x2_h2(unsigned short s) {
    unsigned r;
    asm("cvt.rn.f16x2.e4m3x2 %0, %1;" : "=r"(r) : "h"(s));
    return *(__half2*)&r;
}
__device__ __forceinline__ __half2 as_h2(unsigned w) { return *(__half2*)&w; }

// ---- classic 4x4 GEMM (prep L2 stage only; A transposed, not duplicated) ----
__device__ __forceinline__ void gemm4x4(const float* __restrict__ At, int strideF,
                                        const float* __restrict__ B,
                                        int jc, int rc, float out[4][4]) {
    u64 acc[4][2];
#pragma unroll
    for (int r = 0; r < 4; r++) { acc[r][0] = 0ull; acc[r][1] = 0ull; }
#pragma unroll 16
    for (int k = 0; k < NS; k++) {
        const float4 av = *(const float4*)(At + k * strideF + 4 * rc);
        const float4 bv = *(const float4*)(B  + k * NS      + 4 * jc);
        const u64 c01 = ((const u64*)&bv)[0];
        const u64 c23 = ((const u64*)&bv)[1];
        const u64 a0 = pk2(av.x, av.x), a1 = pk2(av.y, av.y);
        const u64 a2 = pk2(av.z, av.z), a3 = pk2(av.w, av.w);
        acc[0][0] = fma2(c01, a0, acc[0][0]); acc[0][1] = fma2(c23, a0, acc[0][1]);
        acc[1][0] = fma2(c01, a1, acc[1][0]); acc[1][1] = fma2(c23, a1, acc[1][1]);
        acc[2][0] = fma2(c01, a2, acc[2][0]); acc[2][1] = fma2(c23, a2, acc[2][1]);
        acc[3][0] = fma2(c01, a3, acc[3][0]); acc[3][1] = fma2(c23, a3, acc[3][1]);
    }
#pragma unroll
    for (int r = 0; r < 4; r++) {
        upk2(acc[r][0], out[r][0], out[r][1]);
        upk2(acc[r][1], out[r][2], out[r][3]);
    }
}

// ---- duplicated-A 4x4 GEMM: Atd[k*128 + 2r] = Atd[k*128 + 2r+1] = A[r][k] ----
// One LDS.128 delivers two ready-packed f32x2 A operands (no pack MOVs).
__device__ __forceinline__ void gemm4x4_dup(const float* __restrict__ Atd,
                                            const float* __restrict__ B,
                                            int jc, int rc, float out[4][4]) {
    u64 acc[4][2];
#pragma unroll
    for (int r = 0; r < 4; r++) { acc[r][0] = 0ull; acc[r][1] = 0ull; }
#pragma unroll 16
    for (int k = 0; k < NS; k++) {
        const ulonglong2 a01 = *(const ulonglong2*)(Atd + k * 128 + 8 * rc);
        const ulonglong2 a23 = *(const ulonglong2*)(Atd + k * 128 + 8 * rc + 4);
        const float4 bv = *(const float4*)(B + k * NS + 4 * jc);
        const u64 c01 = ((const u64*)&bv)[0];
        const u64 c23 = ((const u64*)&bv)[1];
        acc[0][0] = fma2(c01, a01.x, acc[0][0]); acc[0][1] = fma2(c23, a01.x, acc[0][1]);
        acc[1][0] = fma2(c01, a01.y, acc[1][0]); acc[1][1] = fma2(c23, a01.y, acc[1][1]);
        acc[2][0] = fma2(c01, a23.x, acc[2][0]); acc[2][1] = fma2(c23, a23.x, acc[2][1]);
        acc[3][0] = fma2(c01, a23.y, acc[3][0]); acc[3][1] = fma2(c23, a23.y, acc[3][1]);
    }
#pragma unroll
    for (int r = 0; r < 4; r++) {
        upk2(acc[r][0], out[r][0], out[r][1]);
        upk2(acc[r][1], out[r][2], out[r][3]);
    }
}

// stage transposed global [k*64+r] -> duplicated smem [k*128 + 2r{,+1}], 256 thr
__device__ __forceinline__ void stage_dup(const float* __restrict__ src_t,
                                          float* __restrict__ dst) {
    const int tid = threadIdx.x;
#pragma unroll
    for (int i = 0; i < 4; i++) {
        const int f  = tid + 256 * i;       // float4 index
        const float4 v = ((const float4*)src_t)[f];
        const int k  = f >> 4, r4 = (f & 15) * 4;
        float4* d = (float4*)(dst + k * 128 + 2 * r4);
        d[0] = make_float4(v.x, v.x, v.y, v.y);
        d[1] = make_float4(v.z, v.z, v.w, v.w);
    }
}
__device__ __forceinline__ void stage_nrm(const float* __restrict__ src,
                                          float* __restrict__ dst) {
    const int tid = threadIdx.x;
#pragma unroll
    for (int i = 0; i < 4; i++)
        ((float4*)dst)[tid + 256 * i] = ((const float4*)src)[tid + 256 * i];
}

// ============================================================================
// prep: softmaxes + L1 + L2 (4 products) in ONE kernel, 1024 threads
// dynamic smem: sL1n [2][4096] | sL1t [2][64*68]
// ============================================================================
__global__ void __launch_bounds__(1024)
prep_kernel(const float* __restrict__ Tr,
            const float* __restrict__ Em,
            const float* __restrict__ Pi) {
    extern __shared__ float dynP[];
    float* sL1n = dynP;              // 8192 floats
    float* sL1t = dynP + 8192;       // 2 * 4352 floats (stride 68)

    __shared__ float rowm[NS], rowinv[NS];
    __shared__ float sE[2][NS];
    __shared__ float sred[32];
    __shared__ float sbcA[4];
    __shared__ int   seiA[4];

    const int tid  = threadIdx.x;
    const int lane = tid & 31;
    const int w    = tid >> 5;

    if (tid == 0) { g_acc = 0.0; g_done = 0u; }

#pragma unroll
    for (int rr = 0; rr < 2; rr++) {
        const int r = w + rr * 32;
        const float v0 = Tr[r * NS + lane];
        const float v1 = Tr[r * NS + lane + 32];
        float m = fmaxf(v0, v1);
#pragma unroll
        for (int off = 16; off > 0; off >>= 1)
            m = fmaxf(m, __shfl_xor_sync(0xffffffffu, m, off));
        const float e0 = expf(v0 - m), e1v = expf(v1 - m);
        float s = e0 + e1v;
#pragma unroll
        for (int off = 16; off > 0; off >>= 1)
            s += __shfl_xor_sync(0xffffffffu, s, off);
        if (lane == 0) { rowm[r] = m; rowinv[r] = 1.f / s; }
    }
    if (tid < NS) {
        const float a = Em[tid * 2 + 0], b2 = Em[tid * 2 + 1];
        const float mm = fmaxf(a, b2);
        const float ea = expf(a - mm), eb = expf(b2 - mm);
        const float is = 1.f / (ea + eb);
        sE[0][tid] = ea * is;  sE[1][tid] = eb * is;
        g_E0[tid] = ea * is;   g_E1[tid] = eb * is;
    }
    if (w == 1) {
        const float v0 = Pi[lane], v1 = Pi[lane + 32];
        float m = fmaxf(v0, v1);
#pragma unroll
        for (int off = 16; off > 0; off >>= 1)
            m = fmaxf(m, __shfl_xor_sync(0xffffffffu, m, off));
        const float e0 = expf(v0 - m), e1v = expf(v1 - m);
        float s = e0 + e1v;
#pragma unroll
        for (int off = 16; off > 0; off >>= 1)
            s += __shfl_xor_sync(0xffffffffu, s, off);
        const float inv = 1.f / s;
        g_Pi[lane] = e0 * inv;  g_Pi[lane + 32] = e1v * inv;
    }
    __syncthreads();

    for (int y = 0; y < 2; y++) {
        float vv[4], vmax = 0.f;
#pragma unroll
        for (int i = 0; i < 4; i++) {
            const int idx = tid + i * 1024;
            const int k = idx >> 6, o = idx & 63;
            const float v = expf(Tr[idx] - rowm[k]) * rowinv[k] * sE[y][o];
            vv[i] = v; vmax = fmaxf(vmax, v);
        }
#pragma unroll
        for (int off = 16; off > 0; off >>= 1)
            vmax = fmaxf(vmax, __shfl_xor_sync(0xffffffffu, vmax, off));
        if (lane == 0) sred[w] = vmax;
        __syncthreads();
        if (tid < 32) {
            float m = sred[lane];
#pragma unroll
            for (int off = 16; off > 0; off >>= 1)
                m = fmaxf(m, __shfl_xor_sync(0xffffffffu, m, off));
            if (lane == 0) {
                const int e = (__float_as_int(m) >> 23) - 127;
                seiA[y] = e;  g_e1[y] = e;
                sbcA[y] = __int_as_float((127 - e) << 23);
            }
        }
        __syncthreads();
        const float sc = sbcA[y];
#pragma unroll
        for (int i = 0; i < 4; i++) {
            const int idx = tid + i * 1024;
            const int k = idx >> 6, o = idx & 63;
            const float v = vv[i] * sc;
            sL1n[y * 4096 + idx]         = v;
            sL1t[y * 4352 + o * 68 + k]  = v;
            g_L1[y * 4096 + idx]         = v;
        }
        __syncthreads();
    }

    // --- L2[g] = L1[g>>1] @ L1[g&1] : group g = tid>>8 ---
    {
        const int g    = tid >> 8;
        const int gtid = tid & 255;
        const int jc   = gtid & 15;
        const int rc   = gtid >> 4;
        float out[4][4];
        gemm4x4(sL1t + (g >> 1) * 4352, 68, sL1n + (g & 1) * 4096, jc, rc, out);
        float mx = 0.f;
#pragma unroll
        for (int r = 0; r < 4; r++)
#pragma unroll
            for (int c = 0; c < 4; c++) mx = fmaxf(mx, out[r][c]);
#pragma unroll
        for (int off = 16; off > 0; off >>= 1)
            mx = fmaxf(mx, __shfl_xor_sync(0xffffffffu, mx, off));
        if (lane == 0) sred[w] = mx;
        __syncthreads();
        if (tid < 4) {
            float m = sred[8 * tid];
#pragma unroll
            for (int q = 1; q < 8; q++) m = fmaxf(m, sred[8 * tid + q]);
            const int e = (__float_as_int(m) >> 23) - 127;
            sbcA[tid] = __int_as_float((127 - e) << 23);
            g_e2[tid] = seiA[tid >> 1] + seiA[tid & 1] + e;
        }
        __syncthreads();
        const float sc = sbcA[g];
#pragma unroll
        for (int r = 0; r < 4; r++) {
            float4 wv = make_float4(out[r][0] * sc, out[r][1] * sc,
                                    out[r][2] * sc, out[r][3] * sc);
            *(float4*)(g_L2 + g * 4096 + (4 * rc + r) * NS + 4 * jc) = wv;
        }
#pragma unroll
        for (int c = 0; c < 4; c++) {
            float4 wv = make_float4(out[0][c] * sc, out[1][c] * sc,
                                    out[2][c] * sc, out[3][c] * sc);
            *(float4*)(g_L2t + g * 4096 + (4 * jc + c) * NS + 4 * rc) = wv;
        }
    }
}

// ============================================================================
// combine stage1 (grid 24): c<16: L4[c]=L2[c>>2]@L2[c&3] (+L4t)
//                           c>=16: v=c-16: L3[v]=L2[v>>1]@L1[v&1] (normal only)
// combine stage2 (grid 256): L8t[c] = L4[c>>4]@L4[c&15] (transposed only)
// dyn smem: Atd 8192 floats | Bn 4096 floats (48KB)
// ============================================================================
__global__ void __launch_bounds__(256) combine_kernel(int stage) {
    extern __shared__ float dynC[];
    float* Atd = dynC;            // duplicated transposed A
    float* Bn  = dynC + 8192;

    __shared__ float sred[8];
    __shared__ float sbc;
    __shared__ int   sei;

    const int c = blockIdx.x;
    const int tid  = threadIdx.x;
    const int lane = tid & 31;
    const int w    = tid >> 5;
    const int jc   = tid & 15;
    const int rc   = tid >> 4;

    const float *Asrc_t, *Bsrc; int eIn;
    if (stage == 1) {
        if (c < 16) { Asrc_t = g_L2t + (c >> 2) * 4096; Bsrc = g_L2 + (c & 3) * 4096;
                      eIn = g_e2[c >> 2] + g_e2[c & 3]; }
        else        { const int v = c - 16;
                      Asrc_t = g_L2t + (v >> 1) * 4096; Bsrc = g_L1 + (v & 1) * 4096;
                      eIn = g_e2[v >> 1] + g_e1[v & 1]; }
    } else {
        Asrc_t = g_L4t + (c >> 4) * 4096; Bsrc = g_L4 + (c & 15) * 4096;
        eIn = g_e4[c >> 4] + g_e4[c & 15];
    }

    stage_dup(Asrc_t, Atd);
    stage_nrm(Bsrc, Bn);
    __syncthreads();

    float out[4][4];
    gemm4x4_dup(Atd, Bn, jc, rc, out);
    float mx = 0.f;
#pragma unroll
    for (int r = 0; r < 4; r++)
#pragma unroll
        for (int cc = 0; cc < 4; cc++) mx = fmaxf(mx, out[r][cc]);
#pragma unroll
    for (int off = 16; off > 0; off >>= 1)
        mx = fmaxf(mx, __shfl_xor_sync(0xffffffffu, mx, off));
    if (lane == 0) sred[w] = mx;
    __syncthreads();
    if (tid == 0) {
        float m = sred[0];
#pragma unroll
        for (int q = 1; q < 8; q++) m = fmaxf(m, sred[q]);
        const int e = (__float_as_int(m) >> 23) - 127;
        sbc = __int_as_float((127 - e) << 23);
        sei = e;
    }
    __syncthreads();
    const float sc = sbc;

    if (stage == 1) {
        if (c < 16) {
#pragma unroll
            for (int r = 0; r < 4; r++) {
                float4 wv = make_float4(out[r][0] * sc, out[r][1] * sc,
                                        out[r][2] * sc, out[r][3] * sc);
                *(float4*)(g_L4 + c * 4096 + (4 * rc + r) * NS + 4 * jc) = wv;
            }
#pragma unroll
            for (int cc = 0; cc < 4; cc++) {
                float4 wv = make_float4(out[0][cc] * sc, out[1][cc] * sc,
                                        out[2][cc] * sc, out[3][cc] * sc);
                *(float4*)(g_L4t + c * 4096 + (4 * jc + cc) * NS + 4 * rc) = wv;
            }
            if (tid == 0) g_e4[c] = eIn + sei;
        } else {
            const int v = c - 16;
#pragma unroll
            for (int r = 0; r < 4; r++) {
                float4 wv = make_float4(out[r][0] * sc, out[r][1] * sc,
                                        out[r][2] * sc, out[r][3] * sc);
                *(float4*)(g_L3 + v * 4096 + (4 * rc + r) * NS + 4 * jc) = wv;
            }
            if (tid == 0) g_e3[v] = eIn + sei;
        }
    } else {
#pragma unroll
        for (int cc = 0; cc < 4; cc++) {
            float4 wv = make_float4(out[0][cc] * sc, out[1][cc] * sc,
                                    out[2][cc] * sc, out[3][cc] * sc);
            *(float4*)(g_L8t + c * 4096 + (4 * jc + cc) * NS + 4 * rc) = wv;
        }
        if (tid == 0) g_e8[c] = eIn + sei;
    }
}

// ============================================================================
// final (grid 2048): code = blockIdx.x; P = L8[code>>3] @ L3[code&7]
// one dup-GEMM, normalize, permuted e4m3 write + g_e11
// ============================================================================
__global__ void __launch_bounds__(256) final_kernel() {
    extern __shared__ float dynF[];
    float* Atd = dynF;            // 8192 floats
    float* Bn  = dynF + 8192;     // 4096 floats

    __shared__ float sred[8];
    __shared__ float sbc;
    __shared__ int   sei;

    const int code = blockIdx.x;
    const int a = code >> 3;
    const int b = code & 7;
    const int tid  = threadIdx.x;
    const int lane = tid & 31;
    const int w    = tid >> 5;
    const int jc   = tid & 15;
    const int rc   = tid >> 4;

    stage_dup(g_L8t + a * 4096, Atd);
    stage_nrm(g_L3 + b * 4096, Bn);
    __syncthreads();

    // out[r][cc]: row k = 4rc+r (input state), col o = 4jc+cc
    float out[4][4];
    gemm4x4_dup(Atd, Bn, jc, rc, out);
    float mx = 0.f;
#pragma unroll
    for (int r = 0; r < 4; r++)
#pragma unroll
        for (int cc = 0; cc < 4; cc++) mx = fmaxf(mx, out[r][cc]);
#pragma unroll
    for (int off = 16; off > 0; off >>= 1)
        mx = fmaxf(mx, __shfl_xor_sync(0xffffffffu, mx, off));
    if (lane == 0) sred[w] = mx;
    __syncthreads();
    if (tid == 0) {
        float m = sred[0];
#pragma unroll
        for (int q = 1; q < 8; q++) m = fmaxf(m, sred[q]);
        const int e = (__float_as_int(m) >> 23) - 127;
        sbc = __int_as_float((127 - e) << 23);
        sei = e;
    }
    __syncthreads();
    const float sc = sbc;

    const int k0 = 4 * rc;
#pragma unroll
    for (int cc = 0; cc < 4; cc++) {
        const int o = 4 * jc + cc;
        const unsigned p01 = f2_e4m3x2(out[1][cc] * sc, out[0][cc] * sc);
        const unsigned p23 = f2_e4m3x2(out[3][cc] * sc, out[2][cc] * sc);
        unsigned* dst = (unsigned*)((char*)g_Pt4 + (size_t)code * 4096
                        + ((o < 32 ? 0 : 4) + (k0 >> 4)) * 512
                        + (o & 31) * 16 + (k0 & 15));
        *dst = p01 | (p23 << 16);
    }
    if (tid == 0) g_e11[code] = g_e8[a] + g_e3[b] + sei;
}

// ============================================================================
// main: one warp per element; inline ballot codes; fp8 table, half2 matvec
// ============================================================================
#define PREFETCH(MB, c)                                                       \
    {                                                                         \
        const uint4* __restrict__ tp = g_Pt4 + (size_t)(c) * 256 + lane;      \
        _Pragma("unroll")                                                     \
        for (int i = 0; i < 8; i++) MB[i] = tp[i * 32];                       \
    }

#define PROC8(u, av0, av1, acc)                                               \
    acc = __hfma2(e4m3x2_h2((unsigned short)(u).x),         as_h2((av0).x), acc); \
    acc = __hfma2(e4m3x2_h2((unsigned short)((u).x >> 16)), as_h2((av0).y), acc); \
    acc = __hfma2(e4m3x2_h2((unsigned short)(u).y),         as_h2((av0).z), acc); \
    acc = __hfma2(e4m3x2_h2((unsigned short)((u).y >> 16)), as_h2((av0).w), acc); \
    acc = __hfma2(e4m3x2_h2((unsigned short)(u).z),         as_h2((av1).x), acc); \
    acc = __hfma2(e4m3x2_h2((unsigned short)((u).z >> 16)), as_h2((av1).y), acc); \
    acc = __hfma2(e4m3x2_h2((unsigned short)(u).w),         as_h2((av1).z), acc); \
    acc = __hfma2(e4m3x2_h2((unsigned short)((u).w >> 16)), as_h2((av1).w), acc);

#define PACKSTORE(PP)                                                         \
    {                                                                         \
        const float ev = __shfl_sync(0xffffffffu, s_lo, 0);                   \
        int e = (__float_as_int(ev) >> 23) - 125;                             \
        e = max(-120, min(120, e));                                           \
        const float rsc = __int_as_float((127 - e) << 23);                    \
        s_lo *= rsc; s_hi *= rsc; ce += e;                                    \
        const float lo0 = __shfl_sync(0xffffffffu, s_lo, (2 * lane) & 31);    \
        const float lo1 = __shfl_sync(0xffffffffu, s_lo, (2 * lane + 1) & 31);\
        const float hi0 = __shfl_sync(0xffffffffu, s_hi, (2 * lane) & 31);    \
        const float hi1 = __shfl_sync(0xffffffffu, s_hi, (2 * lane + 1) & 31);\
        const float x0 = lane < 16 ? lo0 : hi0;                               \
        const float x1 = lane < 16 ? lo1 : hi1;                               \
        s_ah[wid][PP][lane] = __floats2half2_rn(x0, x1);                      \
        __syncwarp();                                                         \
    }

#define COMPUTE(MB, CODE)                                                     \
    {                                                                         \
        const uint4* __restrict__ ah = (const uint4*)s_ah[wid][p];            \
        uint4 au[8];                                                          \
        _Pragma("unroll")                                                     \
        for (int q = 0; q < 8; q++) au[q] = ah[q];                            \
        __half2 c0 = __float2half2_rn(0.f), c1 = c0, c2 = c0, c3 = c0;        \
        __half2 d0 = c0, d1 = c0, d2 = c0, d3 = c0;                           \
        PROC8(MB[0], au[0], au[1], c0)                                        \
        PROC8(MB[1], au[2], au[3], c1)                                        \
        PROC8(MB[2], au[4], au[5], c2)                                        \
        PROC8(MB[3], au[6], au[7], c3)                                        \
        PROC8(MB[4], au[0], au[1], d0)                                        \
        PROC8(MB[5], au[2], au[3], d1)                                        \
        PROC8(MB[6], au[4], au[5], d2)                                        \
        PROC8(MB[7], au[6], au[7], d3)                                        \
        const __half2 tc = __hadd2(__hadd2(c0, c1), __hadd2(c2, c3));         \
        const __half2 td = __hadd2(__hadd2(d0, d1), __hadd2(d2, d3));         \
        s_lo = __low2float(tc) + __high2float(tc);                            \
        s_hi = __low2float(td) + __high2float(td);                            \
        ce += g_e11[CODE];                                                    \
        p ^= 1;                                                               \
        PACKSTORE(p)                                                          \
    }

__device__ __forceinline__ int getcode(const unsigned* __restrict__ bw, int j) {
    const int base = 1 + LBLK * j;
    const unsigned lo = bw[base >> 5];
    const unsigned hi = bw[(base >> 5) + 1];
    return (int)(__brev(__funnelshift_r(lo, hi, base & 31)) >> 21);
}

__global__ void __launch_bounds__(128)
hmm_main_kernel(const int* __restrict__ y, float* __restrict__ outp) {
    __shared__ __align__(16) __half2 s_ah[4][2][32];
    __shared__ unsigned s_bw[4][34];

    const int tid  = threadIdx.x;
    const int lane = tid & 31;
    const int wid  = tid >> 5;
    const int b    = blockIdx.x * 4 + wid;
    const int* __restrict__ yrow = y + b * DIM;

#pragma unroll
    for (int ch = 0; ch < 32; ch++) {
        const unsigned w = __ballot_sync(0xffffffffu, yrow[ch * 32 + lane]);
        if (lane == 0) s_bw[wid][ch] = w;
    }
    if (lane == 0) { s_bw[wid][32] = 0u; s_bw[wid][33] = 0u; }
    __syncwarp();
    const unsigned* __restrict__ bw = s_bw[wid];

    const int y0 = (int)(bw[0] & 1u);
    float s_lo = g_Pi[lane]      * (y0 ? g_E1[lane]      : g_E0[lane]);
    float s_hi = g_Pi[lane + 32] * (y0 ? g_E1[lane + 32] : g_E0[lane + 32]);

    int ce = 0, p = 0;
    PACKSTORE(0)

    uint4 mA[8], mB[8];
    int cA = getcode(bw, 0), cB;
    PREFETCH(mA, cA)

    for (int jj = 0; jj < 92; jj += 2) {
        cB = getcode(bw, jj + 1);
        PREFETCH(mB, cB)
        COMPUTE(mA, cA)
        cA = getcode(bw, jj + 2);
        PREFETCH(mA, cA)
        COMPUTE(mB, cB)
    }
    COMPUTE(mA, cA)   // j = 92 (prefetched at jj = 90)

    float v = s_lo + s_hi;
#pragma unroll
    for (int off = 16; off > 0; off >>= 1)
        v += __shfl_xor_sync(0xffffffffu, v, off);

    if (lane == 0) {
        const double logp = (double)logf(v) + (double)ce * 0.6931471805599453;
        atomicAdd(&g_acc, logp);
        __threadfence();
        const unsigned done = atomicAdd(&g_done, 1u);
        if (done == (unsigned)(BATCH - 1)) {
            outp[0] = (float)(g_acc * (1.0 / 4096.0));
        }
    }
}

extern "C" void kernel_launch(void* const* d_in, const int* in_sizes, int n_in,
                              void* d_out, int out_size) {
    const int*   y  = (const int*)  d_in[0];
    const float* Tr = (const float*)d_in[1];
    const float* Em = (const float*)d_in[2];
    const float* Pi = (const float*)d_in[3];

    cudaFuncSetAttribute(prep_kernel,
        cudaFuncAttributeMaxDynamicSharedMemorySize, 67584);
    cudaFuncSetAttribute(combine_kernel,
        cudaFuncAttributeMaxDynamicSharedMemorySize, 49152);
    cudaFuncSetAttribute(final_kernel,
        cudaFuncAttributeMaxDynamicSharedMemorySize, 49152);

    prep_kernel<<<1, 1024, 67584>>>(Tr, Em, Pi);
    combine_kernel<<<24, 256, 49152>>>(1);    // L4 (+L4t) and L3
    combine_kernel<<<256, 256, 49152>>>(2);   // L8t
    final_kernel<<<2048, 256, 49152>>>();     // e4m3 table + e11
    hmm_main_kernel<<<BATCH / 4, 128>>>(y, (float*)d_out);
}